// round 10
// baseline (speedup 1.0000x reference)
#include <cuda_runtime.h>
#include <cuda_bf16.h>
#include <cstdint>

// ---------------------------------------------------------------------------
// KAN 3-layer (12->64->64->24), warp-specialized: warps 0-3 run bf16 3-pass
// mma.sync (hi/lo split), warps 4-7 generate spline features into K-major
// swizzled SMEM. Named-barrier (arrive/sync) pipeline, B via cp.async.
// R10 fix: consumer-only barrier before B refill (R9 had a B-buffer race).
// ---------------------------------------------------------------------------

#define MAXN (32 * 64 * 64)

__device__ float g_h1[64 * MAXN];
__device__ float g_h2[64 * MAXN];
__device__ __align__(16) __nv_bfloat16 g_Whi0[64 * 128];
__device__ __align__(16) __nv_bfloat16 g_Wlo0[64 * 128];
__device__ __align__(16) __nv_bfloat16 g_Whi1[64 * 576];
__device__ __align__(16) __nv_bfloat16 g_Wlo1[64 * 576];
__device__ __align__(16) __nv_bfloat16 g_Whi2[24 * 576];
__device__ __align__(16) __nv_bfloat16 g_Wlo2[24 * 576];

// ------------------------------- helpers -----------------------------------

__device__ __forceinline__ uint32_t smem_u32(const void* p) {
    uint32_t a;
    asm("{ .reg .u64 t; cvta.to.shared.u64 t, %1; cvt.u32.u64 %0, t; }"
        : "=r"(a) : "l"(p));
    return a;
}
__device__ __forceinline__ uint32_t sw128(uint32_t off) {
    return off ^ ((off >> 3) & 0x70);
}
// K-major A tile: AT[k][m], 256B per k-row, per-k XOR swizzle in 128B halves
__device__ __forceinline__ uint32_t swAT(int k, int m) {
    uint32_t off = (uint32_t)(m * 2);
    return (uint32_t)(k * 256) + (off & 0x80u) +
           ((off & 0x7Fu) ^ (((uint32_t)k & 7u) << 4));
}
__device__ __forceinline__ void ldsm4(uint32_t addr, uint32_t r[4]) {
    asm volatile("ldmatrix.sync.aligned.m8n8.x4.shared.b16 {%0,%1,%2,%3}, [%4];"
                 : "=r"(r[0]), "=r"(r[1]), "=r"(r[2]), "=r"(r[3]) : "r"(addr));
}
__device__ __forceinline__ void ldsm4t(uint32_t addr, uint32_t r[4]) {
    asm volatile("ldmatrix.sync.aligned.m8n8.x4.trans.shared.b16 {%0,%1,%2,%3}, [%4];"
                 : "=r"(r[0]), "=r"(r[1]), "=r"(r[2]), "=r"(r[3]) : "r"(addr));
}
__device__ __forceinline__ void ldsm2(uint32_t addr, uint32_t r[2]) {
    asm volatile("ldmatrix.sync.aligned.m8n8.x2.shared.b16 {%0,%1}, [%2];"
                 : "=r"(r[0]), "=r"(r[1]) : "r"(addr));
}
__device__ __forceinline__ void mma16816(float c[4], const uint32_t a[4],
                                         uint32_t b0, uint32_t b1) {
    asm volatile(
        "mma.sync.aligned.m16n8k16.row.col.f32.bf16.bf16.f32 "
        "{%0,%1,%2,%3},{%4,%5,%6,%7},{%8,%9},{%0,%1,%2,%3};"
        : "+f"(c[0]), "+f"(c[1]), "+f"(c[2]), "+f"(c[3])
        : "r"(a[0]), "r"(a[1]), "r"(a[2]), "r"(a[3]), "r"(b0), "r"(b1));
}
__device__ __forceinline__ void sts16(uint32_t addr, unsigned short v) {
    asm volatile("st.shared.b16 [%0], %1;" :: "r"(addr), "h"(v));
}
__device__ __forceinline__ void cp16(uint32_t dst, const void* src) {
    asm volatile("cp.async.ca.shared.global [%0], [%1], 16;"
                 :: "r"(dst), "l"(src) : "memory");
}
__device__ __forceinline__ void cp_commit() {
    asm volatile("cp.async.commit_group;" ::: "memory");
}
__device__ __forceinline__ void cp_wait0() {
    asm volatile("cp.async.wait_group 0;" ::: "memory");
}
__device__ __forceinline__ void cp_wait1() {
    asm volatile("cp.async.wait_group 1;" ::: "memory");
}
// 256-wide named barrier: waiters block, signalers just arrive
__device__ __forceinline__ void bar_wait(int id) {
    asm volatile("bar.sync %0, 256;" :: "r"(id) : "memory");
}
__device__ __forceinline__ void bar_arrive(int id) {
    asm volatile("bar.arrive %0, 256;" :: "r"(id) : "memory");
}
// consumer-only rendezvous (128 threads: warps 0-3)
__device__ __forceinline__ void bar_cons() {
    asm volatile("bar.sync 6, 128;" ::: "memory");
}
__device__ __forceinline__ void split_hl(float v, unsigned short& h, unsigned short& l) {
    __nv_bfloat16 hb = __float2bfloat16(v);
    float hf = __bfloat162float(hb);
    __nv_bfloat16 lb = __float2bfloat16(v - hf);
    h = __bfloat16_as_ushort(hb);
    l = __bfloat16_as_ushort(lb);
}

// ------------------------------- fold kernel (fused, all 3 layers) ---------
__global__ void fold_all(const float* c0, const float* b0, const float* s0,
                         const float* c1, const float* b1, const float* s1,
                         const float* c2, const float* b2, const float* s2,
                         __nv_bfloat16* Whi0, __nv_bfloat16* Wlo0,
                         __nv_bfloat16* Whi1, __nv_bfloat16* Wlo1,
                         __nv_bfloat16* Whi2, __nv_bfloat16* Wlo2) {
    int idx = blockIdx.x * blockDim.x + threadIdx.x;
    const float *coef, *sbp, *ss;
    __nv_bfloat16 *Whi, *Wlo;
    int IN, OUT, KPAD;
    if (idx < 64 * 128) {
        coef = c0; sbp = b0; ss = s0; Whi = Whi0; Wlo = Wlo0;
        IN = 12; OUT = 64; KPAD = 128;
    } else if (idx < 64 * 128 + 64 * 576) {
        idx -= 64 * 128;
        coef = c1; sbp = b1; ss = s1; Whi = Whi1; Wlo = Wlo1;
        IN = 64; OUT = 64; KPAD = 576;
    } else if (idx < 64 * 128 + 64 * 576 + 24 * 576) {
        idx -= 64 * 128 + 64 * 576;
        coef = c2; sbp = b2; ss = s2; Whi = Whi2; Wlo = Wlo2;
        IN = 64; OUT = 24; KPAD = 576;
    } else return;
    int o = idx / KPAD, k = idx % KPAD;
    float w = 0.0f;
    if (k < IN * 9) {
        int i = k / 9, j = k % 9;
        w = (j == 0) ? sbp[i * OUT + o] : coef[(i * OUT + o) * 8 + (j - 1)] * ss[i * OUT + o];
    }
    __nv_bfloat16 hi = __float2bfloat16(w);
    __nv_bfloat16 lo = __float2bfloat16(w - __bfloat162float(hi));
    Whi[idx] = hi;
    Wlo[idx] = lo;
}

// ------------------------------- layer kernel ------------------------------
template <int IN, int OUT, int K, int KPAD, int NCHUNK, bool IN_NCHW, bool OUT_NCHW>
__global__ void __launch_bounds__(256, 2)
kan_ws(const float* __restrict__ hin, const float* __restrict__ grid,
       const __nv_bfloat16* __restrict__ Whi, const __nv_bfloat16* __restrict__ Wlo,
       float* __restrict__ hout, int N) {
    constexpr int NT = OUT / 8;
    constexpr int NT2 = NT / 2;
    constexpr int ABUF = 64 * 256;   // 16KB per A buffer
    constexpr int BBUF = OUT * 128;

    extern __shared__ char dsm[];
    const uint32_t sb = smem_u32(dsm);
    const uint32_t BBASE = sb + 4 * ABUF;

    const int tid = threadIdx.x;
    const int wid = tid >> 5;
    const int lane = tid & 31;
    const int row0 = blockIdx.x * 128;

    float acc[2][NT][4];  // only consumers use

    if (wid < 4) {
        // ======================= CONSUMER (warps 0-3) ======================
        const int gq = lane >> 3;
        const int a_k = (lane & 7) + ((gq >> 1) * 8);
        const int a_m0 = wid * 32 + (gq & 1) * 8;
        const uint32_t a_sw0 = swAT(a_k, a_m0);
        const uint32_t a_sw1 = swAT(a_k, a_m0 + 16);
        const int brow = (lane & 7) + 8 * (gq >> 1);
        const int bseg = gq & 1;

#pragma unroll
        for (int mt = 0; mt < 2; mt++)
#pragma unroll
            for (int p = 0; p < NT; p++)
#pragma unroll
                for (int q = 0; q < 4; q++) acc[mt][p][q] = 0.0f;

        auto stageB = [&](int c, int st) {
            uint32_t bb = BBASE + (uint32_t)(st * 2) * BBUF;
            for (int v = tid; v < OUT * 16; v += 128) {
                int h = v >= OUT * 8;
                int u = v - (h ? OUT * 8 : 0);
                int o = u >> 3, seg = u & 7;
                const __nv_bfloat16* src = (h ? Wlo : Whi) + o * KPAD + c * 64 + seg * 8;
                cp16(bb + (uint32_t)h * BBUF + sw128((uint32_t)(o * 128 + seg * 16)), src);
            }
            cp_commit();
        };

        stageB(0, 0);
        if (NCHUNK > 1) stageB(1, 1);

        for (int c = 0; c < NCHUNK; c++) {
            const int st = c & 1;
            if (c + 1 < NCHUNK) cp_wait1(); else cp_wait0();
            bar_wait(1 + st);  // FULL(st): producers filled A(c)

            const uint32_t Ah = sb + (uint32_t)(st * 2) * ABUF;
            const uint32_t Al = Ah + ABUF;
            const uint32_t Bh = BBASE + (uint32_t)(st * 2) * BBUF;
            const uint32_t Bl = Bh + BBUF;
#pragma unroll
            for (int ks = 0; ks < 4; ks++) {
                const uint32_t ko = (uint32_t)(ks * 4096);
                uint32_t ah0[4], al0[4], ah1[4], al1[4];
                ldsm4t(Ah + a_sw0 + ko, ah0);
                ldsm4t(Al + a_sw0 + ko, al0);
                ldsm4t(Ah + a_sw1 + ko, ah1);
                ldsm4t(Al + a_sw1 + ko, al1);
#pragma unroll
                for (int q = 0; q < NT2; q++) {
                    uint32_t bo = sw128((uint32_t)((16 * q + brow) * 128 + bseg * 16 + ks * 32));
                    uint32_t bh[4], bl[4];
                    ldsm4(Bh + bo, bh);
                    ldsm4(Bl + bo, bl);
                    mma16816(acc[0][2 * q], ah0, bh[0], bh[1]);
                    mma16816(acc[0][2 * q + 1], ah0, bh[2], bh[3]);
                    mma16816(acc[0][2 * q], ah0, bl[0], bl[1]);
                    mma16816(acc[0][2 * q + 1], ah0, bl[2], bl[3]);
                    mma16816(acc[0][2 * q], al0, bh[0], bh[1]);
                    mma16816(acc[0][2 * q + 1], al0, bh[2], bh[3]);
                    mma16816(acc[1][2 * q], ah1, bh[0], bh[1]);
                    mma16816(acc[1][2 * q + 1], ah1, bh[2], bh[3]);
                    mma16816(acc[1][2 * q], ah1, bl[0], bl[1]);
                    mma16816(acc[1][2 * q + 1], ah1, bl[2], bl[3]);
                    mma16816(acc[1][2 * q], al1, bh[0], bh[1]);
                    mma16816(acc[1][2 * q + 1], al1, bh[2], bh[3]);
                }
                if constexpr (NT & 1) {
                    uint32_t bo = sw128((uint32_t)((8 * (NT - 1) + (lane & 7)) * 128 +
                                                   ((lane >> 3) & 1) * 16 + ks * 32));
                    uint32_t bh2[2], bl2[2];
                    ldsm2(Bh + bo, bh2);
                    ldsm2(Bl + bo, bl2);
                    mma16816(acc[0][NT - 1], ah0, bh2[0], bh2[1]);
                    mma16816(acc[0][NT - 1], ah0, bl2[0], bl2[1]);
                    mma16816(acc[0][NT - 1], al0, bh2[0], bh2[1]);
                    mma16816(acc[1][NT - 1], ah1, bh2[0], bh2[1]);
                    mma16816(acc[1][NT - 1], ah1, bl2[0], bl2[1]);
                    mma16816(acc[1][NT - 1], al1, bh2[0], bh2[1]);
                }
            }

            if (c + 2 < NCHUNK) {
                bar_arrive(3 + st);  // EMPTY(st): this thread done with A(st)
                bar_cons();          // ALL consumers done reading B(st)
                stageB(c + 2, st);   // safe to overwrite B(st) now
            }
        }
    } else {
        // ======================= PRODUCER (warps 4-7) ======================
        const int r = tid - 128;  // 0..127, one row per thread
        const int rowg = row0 + r;
        const int img = rowg >> 12;
        const int pix = rowg & 4095;

        const float t0 = __ldg(grid + 0);
        const float invh = 1.0f / (__ldg(grid + 1) - t0);
        const float t11 = __ldg(grid + 11);

        auto prefetch = [&](int c, float* xr) {
            const int klo = c * 64;
            const int ilo = klo / 9;
            int ihi = (klo + 63) / 9;
            if (ihi > IN - 1) ihi = IN - 1;
#pragma unroll
            for (int q = 0; q < 8; q++) {
                int i = ilo + q;
                int idx;
                if (IN_NCHW) idx = (img * IN + i) * 4096 + pix;
                else idx = i * N + rowg;
                xr[q] = (i <= ihi) ? __ldg(hin + idx) : 0.0f;
            }
        };

        auto scatter = [&](int c, int st, const float* xr) {
            const uint32_t ah = sb + (uint32_t)(st * 2) * ABUF;
            const int klo = c * 64;
            const int ilo = klo / 9;
            int ihi = (klo + 63) / 9;
            if (ihi > IN - 1) ihi = IN - 1;
#pragma unroll
            for (int q = 0; q < 8; q++) {
                int i = ilo + q;
                if (i > ihi) break;
                float x = xr[q];
                float f0 = __fdividef(x, 1.0f + __expf(-x));  // silu

                bool inr = (x >= t0) && (x < t11);
                float s = (x - t0) * invh;
                s = fminf(fmaxf(s, 0.0f), 10.999f);
                int m = (int)s;
                float u1 = s - (float)m;
                float um = 1.0f - u1;
                float u2 = u1 * u1, u3 = u2 * u1;
                float fl = inr ? (1.0f / 6.0f) : 0.0f;
                float v0 = um * um * um * fl;
                float v1 = (3.0f * u3 - 6.0f * u2 + 4.0f) * fl;
                float v2 = (-3.0f * u3 + 3.0f * u2 + 3.0f * u1 + 1.0f) * fl;
                float v3 = u3 * fl;

                const int kb = i * 9 - klo;
                unsigned short hh, ll;
                if ((unsigned)kb < 64u) {  // silu slot (j=0)
                    split_hl(f0, hh, ll);
                    uint32_t off = swAT(kb, r);
                    sts16(ah + off, hh);
                    sts16(ah + ABUF + off, ll);
                }
                // window values at slot (bi mod 8); zero value if bi invalid
#pragma unroll
                for (int g = 0; g < 4; g++) {
                    int bi = m - 3 + g;
                    int slot = (bi + 8) & 7;
                    int k = kb + 1 + slot;
                    float v = (g == 0) ? v0 : (g == 1) ? v1 : (g == 2) ? v2 : v3;
                    v = ((unsigned)bi <= 7u) ? v : 0.0f;
                    if ((unsigned)k < 64u) {
                        split_hl(v, hh, ll);
                        uint32_t off = swAT(k, r);
                        sts16(ah + off, hh);
                        sts16(ah + ABUF + off, ll);
                    }
                }
                // complement slots get zero: (m+1..m+4) mod 8
#pragma unroll
                for (int t = 0; t < 4; t++) {
                    int slot = (m + 1 + t) & 7;
                    int k = kb + 1 + slot;
                    if ((unsigned)k < 64u) {
                        uint32_t off = swAT(k, r);
                        sts16(ah + off, 0);
                        sts16(ah + ABUF + off, 0);
                    }
                }
            }
            if (K < KPAD && c == NCHUNK - 1) {  // layer0 tail zero cols
#pragma unroll
                for (int kk = (K & 63); kk < 64; kk++) {
                    uint32_t off = swAT(kk, r);
                    sts16(ah + off, 0);
                    sts16(ah + ABUF + off, 0);
                }
            }
        };

        float xa[8], xb[8];
        prefetch(0, xa);
        if (NCHUNK > 1) prefetch(1, xb);

        for (int c = 0; c < NCHUNK; c++) {
            const int st = c & 1;
            if (c >= 2) bar_wait(3 + st);  // EMPTY(st)
            scatter(c, st, (c & 1) ? xb : xa);
            if (c + 2 < NCHUNK) prefetch(c + 2, (c & 1) ? xb : xa);
            bar_arrive(1 + st);  // FULL(st)
        }
    }

    // ---------------- epilogue (converged) ----------------
    __syncthreads();
    constexpr int SP = 132;
    float* S = reinterpret_cast<float*>(dsm);  // reuse A region
    if (wid < 4) {
#pragma unroll
        for (int mt = 0; mt < 2; mt++) {
            const int er0 = wid * 32 + mt * 16 + (lane >> 2);
            const int er1 = er0 + 8;
#pragma unroll
            for (int p = 0; p < NT; p++) {
                int o = p * 8 + (lane & 3) * 2;
                S[o * SP + er0] = acc[mt][p][0];
                S[(o + 1) * SP + er0] = acc[mt][p][1];
                S[o * SP + er1] = acc[mt][p][2];
                S[(o + 1) * SP + er1] = acc[mt][p][3];
            }
        }
    }
    __syncthreads();
    for (int idx = tid; idx < OUT * 128; idx += 256) {
        int o = idx >> 7;
        int rr = idx & 127;
        float val = S[o * SP + rr];
        if (OUT_NCHW) hout[((row0 >> 12) * OUT + o) * 4096 + (row0 & 4095) + rr] = val;
        else hout[o * N + row0 + rr] = val;
    }
}

// ------------------------------- launch ------------------------------------

extern "C" void kernel_launch(void* const* d_in, const int* in_sizes, int n_in,
                              void* d_out, int out_size) {
    const float* x     = (const float*)d_in[0];
    const float* grid0 = (const float*)d_in[1];
    const float* coef0 = (const float*)d_in[2];
    const float* sb0   = (const float*)d_in[3];
    const float* ss0   = (const float*)d_in[4];
    const float* grid1 = (const float*)d_in[5];
    const float* coef1 = (const float*)d_in[6];
    const float* sb1   = (const float*)d_in[7];
    const float* ss1   = (const float*)d_in[8];
    const float* grid2 = (const float*)d_in[9];
    const float* coef2 = (const float*)d_in[10];
    const float* sb2   = (const float*)d_in[11];
    const float* ss2   = (const float*)d_in[12];
    float* out = (float*)d_out;

    int N = in_sizes[0] / 12;
    if (N > MAXN) N = MAXN;

    float *h1, *h2;
    __nv_bfloat16 *Whi0, *Wlo0, *Whi1, *Wlo1, *Whi2, *Wlo2;
    cudaGetSymbolAddress((void**)&h1, g_h1);
    cudaGetSymbolAddress((void**)&h2, g_h2);
    cudaGetSymbolAddress((void**)&Whi0, g_Whi0);
    cudaGetSymbolAddress((void**)&Wlo0, g_Wlo0);
    cudaGetSymbolAddress((void**)&Whi1, g_Whi1);
    cudaGetSymbolAddress((void**)&Wlo1, g_Wlo1);
    cudaGetSymbolAddress((void**)&Whi2, g_Whi2);
    cudaGetSymbolAddress((void**)&Wlo2, g_Wlo2);

    constexpr int FOLD_TOTAL = 64 * 128 + 64 * 576 + 24 * 576;
    fold_all<<<(FOLD_TOTAL + 255) / 256, 256>>>(coef0, sb0, ss0, coef1, sb1, ss1,
                                                coef2, sb2, ss2, Whi0, Wlo0,
                                                Whi1, Wlo1, Whi2, Wlo2);

    auto k0 = kan_ws<12, 64, 108, 128, 2, true, false>;
    auto k1 = kan_ws<64, 64, 576, 576, 9, false, false>;
    auto k2 = kan_ws<64, 24, 576, 576, 9, false, true>;

    constexpr int SM01 = 4 * 64 * 256 + 4 * 64 * 128;  // 98304
    constexpr int SM2  = 4 * 64 * 256 + 4 * 24 * 128;  // 77824
    cudaFuncSetAttribute(k0, cudaFuncAttributeMaxDynamicSharedMemorySize, SM01);
    cudaFuncSetAttribute(k1, cudaFuncAttributeMaxDynamicSharedMemorySize, SM01);
    cudaFuncSetAttribute(k2, cudaFuncAttributeMaxDynamicSharedMemorySize, SM2);

    int blocks = N / 128;
    k0<<<blocks, 256, SM01>>>(x, grid0, Whi0, Wlo0, h1, N);
    k1<<<blocks, 256, SM01>>>(h1, grid1, Whi1, Wlo1, h2, N);
    k2<<<blocks, 256, SM2>>>(h2, grid2, Whi2, Wlo2, out, N);
}

// round 11
// speedup vs baseline: 1.3808x; 1.3808x over previous
#include <cuda_runtime.h>
#include <cuda_fp16.h>
#include <cstdint>

// ---------------------------------------------------------------------------
// KAN 3-layer (12->64->64->24) via warp mma.sync fp16 2-pass (A single fp16,
// B split fp16 hi/lo). 256 threads / 128 rows per CTA, K-major A, mod-8
// full-coverage scatter, cp.async B, ping-pong, 1 barrier per chunk.
// ---------------------------------------------------------------------------

#define MAXN (32 * 64 * 64)

__device__ float g_h1[64 * MAXN];
__device__ float g_h2[64 * MAXN];
__device__ __align__(16) __half g_Whi0[64 * 128];
__device__ __align__(16) __half g_Wlo0[64 * 128];
__device__ __align__(16) __half g_Whi1[64 * 576];
__device__ __align__(16) __half g_Wlo1[64 * 576];
__device__ __align__(16) __half g_Whi2[24 * 576];
__device__ __align__(16) __half g_Wlo2[24 * 576];

// ------------------------------- helpers -----------------------------------

__device__ __forceinline__ uint32_t smem_u32(const void* p) {
    uint32_t a;
    asm("{ .reg .u64 t; cvta.to.shared.u64 t, %1; cvt.u32.u64 %0, t; }"
        : "=r"(a) : "l"(p));
    return a;
}
__device__ __forceinline__ uint32_t sw128(uint32_t off) {
    return off ^ ((off >> 3) & 0x70);
}
// K-major A tile: AT[k][m], 256B per k-row, per-k XOR swizzle in 128B halves
__device__ __forceinline__ uint32_t swAT(int k, int m) {
    uint32_t off = (uint32_t)(m * 2);
    return (uint32_t)(k * 256) + (off & 0x80u) +
           ((off & 0x7Fu) ^ (((uint32_t)k & 7u) << 4));
}
__device__ __forceinline__ void ldsm4(uint32_t addr, uint32_t r[4]) {
    asm volatile("ldmatrix.sync.aligned.m8n8.x4.shared.b16 {%0,%1,%2,%3}, [%4];"
                 : "=r"(r[0]), "=r"(r[1]), "=r"(r[2]), "=r"(r[3]) : "r"(addr));
}
__device__ __forceinline__ void ldsm4t(uint32_t addr, uint32_t r[4]) {
    asm volatile("ldmatrix.sync.aligned.m8n8.x4.trans.shared.b16 {%0,%1,%2,%3}, [%4];"
                 : "=r"(r[0]), "=r"(r[1]), "=r"(r[2]), "=r"(r[3]) : "r"(addr));
}
__device__ __forceinline__ void ldsm2(uint32_t addr, uint32_t r[2]) {
    asm volatile("ldmatrix.sync.aligned.m8n8.x2.shared.b16 {%0,%1}, [%2];"
                 : "=r"(r[0]), "=r"(r[1]) : "r"(addr));
}
__device__ __forceinline__ void mma16816(float c[4], const uint32_t a[4],
                                         uint32_t b0, uint32_t b1) {
    asm volatile(
        "mma.sync.aligned.m16n8k16.row.col.f32.f16.f16.f32 "
        "{%0,%1,%2,%3},{%4,%5,%6,%7},{%8,%9},{%0,%1,%2,%3};"
        : "+f"(c[0]), "+f"(c[1]), "+f"(c[2]), "+f"(c[3])
        : "r"(a[0]), "r"(a[1]), "r"(a[2]), "r"(a[3]), "r"(b0), "r"(b1));
}
__device__ __forceinline__ void sts16(uint32_t addr, unsigned short v) {
    asm volatile("st.shared.b16 [%0], %1;" :: "r"(addr), "h"(v));
}
__device__ __forceinline__ void cp16(uint32_t dst, const void* src) {
    asm volatile("cp.async.ca.shared.global [%0], [%1], 16;"
                 :: "r"(dst), "l"(src) : "memory");
}
__device__ __forceinline__ void cp_commit() {
    asm volatile("cp.async.commit_group;" ::: "memory");
}
__device__ __forceinline__ void cp_wait0() {
    asm volatile("cp.async.wait_group 0;" ::: "memory");
}

// ------------------------------- fold kernel (fused, all 3 layers) ---------
__global__ void fold_all(const float* c0, const float* b0, const float* s0,
                         const float* c1, const float* b1, const float* s1,
                         const float* c2, const float* b2, const float* s2,
                         __half* Whi0, __half* Wlo0,
                         __half* Whi1, __half* Wlo1,
                         __half* Whi2, __half* Wlo2) {
    int idx = blockIdx.x * blockDim.x + threadIdx.x;
    const float *coef, *sbp, *ss;
    __half *Whi, *Wlo;
    int IN, OUT, KPAD;
    if (idx < 64 * 128) {
        coef = c0; sbp = b0; ss = s0; Whi = Whi0; Wlo = Wlo0;
        IN = 12; OUT = 64; KPAD = 128;
    } else if (idx < 64 * 128 + 64 * 576) {
        idx -= 64 * 128;
        coef = c1; sbp = b1; ss = s1; Whi = Whi1; Wlo = Wlo1;
        IN = 64; OUT = 64; KPAD = 576;
    } else if (idx < 64 * 128 + 64 * 576 + 24 * 576) {
        idx -= 64 * 128 + 64 * 576;
        coef = c2; sbp = b2; ss = s2; Whi = Whi2; Wlo = Wlo2;
        IN = 64; OUT = 24; KPAD = 576;
    } else return;
    int o = idx / KPAD, k = idx % KPAD;
    float w = 0.0f;
    if (k < IN * 9) {
        int i = k / 9, j = k % 9;
        w = (j == 0) ? sbp[i * OUT + o] : coef[(i * OUT + o) * 8 + (j - 1)] * ss[i * OUT + o];
    }
    __half hi = __float2half_rn(w);
    __half lo = __float2half_rn(w - __half2float(hi));
    Whi[idx] = hi;
    Wlo[idx] = lo;
}

// ------------------------------- layer kernel ------------------------------
// SMEM: A[stage] 16KB each (K-major, 64 k x 128 m fp16) = 32KB
//       B[stage][hi/lo] OUT*128B each
template <int IN, int OUT, int K, int KPAD, int NCHUNK, bool IN_NCHW, bool OUT_NCHW>
__global__ void __launch_bounds__(256, 2)
kan_mma(const float* __restrict__ hin, const float* __restrict__ grid,
        const __half* __restrict__ Whi, const __half* __restrict__ Wlo,
        float* __restrict__ hout, int N) {
    constexpr int NT = OUT / 8;
    constexpr int NT2 = NT / 2;
    constexpr int ABUF = 64 * 256;   // 16KB per A stage
    constexpr int BBUF = OUT * 128;  // per half (hi or lo)

    extern __shared__ char dsm[];
    const uint32_t sb = smem_u32(dsm);
    const uint32_t BBASE = sb + 2 * ABUF;

    const int tid = threadIdx.x;
    const int wid = tid >> 5;
    const int lane = tid & 31;
    const int row0 = blockIdx.x * 128;

    const float t0 = __ldg(grid + 0);
    const float invh = 1.0f / (__ldg(grid + 1) - t0);
    const float t11 = __ldg(grid + 11);

    const int r = tid & 127;
    const int half_ = tid >> 7;
    const int rowg = row0 + r;
    const int img = rowg >> 12;
    const int pix = rowg & 4095;

    // fragment addressing
    const int gq = lane >> 3;
    const int a_k = (lane & 7) + ((gq >> 1) * 8);
    const int a_m = wid * 16 + (gq & 1) * 8;
    const uint32_t a_sw = swAT(a_k, a_m);  // +ks*4096 per k-step
    const int brow = (lane & 7) + 8 * (gq >> 1);
    const int bseg = gq & 1;

    float acc[NT][4];
#pragma unroll
    for (int p = 0; p < NT; p++)
#pragma unroll
        for (int q = 0; q < 4; q++) acc[p][q] = 0.0f;

    // ---------------- pipeline helpers ----------------
    auto prefetch = [&](int c, float* xr) {
        const int klo = c * 64;
        const int ilo = klo / 9;
        int ihi = (klo + 63) / 9;
        if (ihi > IN - 1) ihi = IN - 1;
#pragma unroll
        for (int q = 0; q < 5; q++) {
            int i = ilo + half_ + 2 * q;
            int idx;
            if (IN_NCHW) idx = (img * IN + i) * 4096 + pix;
            else idx = i * N + rowg;
            xr[q] = (i <= ihi) ? __ldg(hin + idx) : 0.0f;
        }
    };

    auto stageB = [&](int c, int st) {
        uint32_t bb = BBASE + (uint32_t)(st * 2) * BBUF;
        for (int v = tid; v < OUT * 16; v += 256) {
            int h = v >= OUT * 8;
            int u = v - (h ? OUT * 8 : 0);
            int o = u >> 3, seg = u & 7;
            const __half* src = (h ? Wlo : Whi) + o * KPAD + c * 64 + seg * 8;
            cp16(bb + (uint32_t)h * BBUF + sw128((uint32_t)(o * 128 + seg * 16)), src);
        }
        cp_commit();
    };

    auto scatter = [&](int c, int st, const float* xr) {
        const uint32_t ah = sb + (uint32_t)st * ABUF;
        const int klo = c * 64;
        const int ilo = klo / 9;
        int ihi = (klo + 63) / 9;
        if (ihi > IN - 1) ihi = IN - 1;
#pragma unroll
        for (int q = 0; q < 5; q++) {
            int i = ilo + half_ + 2 * q;
            if (i > ihi) break;
            float x = xr[q];
            float f0 = __fdividef(x, 1.0f + __expf(-x));  // silu

            bool inr = (x >= t0) && (x < t11);
            float s = (x - t0) * invh;
            s = fminf(fmaxf(s, 0.0f), 10.999f);
            int m = (int)s;
            float u1 = s - (float)m;
            float um = 1.0f - u1;
            float u2 = u1 * u1, u3 = u2 * u1;
            float fl = inr ? (1.0f / 6.0f) : 0.0f;
            float v0 = um * um * um * fl;
            float v1 = (3.0f * u3 - 6.0f * u2 + 4.0f) * fl;
            float v2 = (-3.0f * u3 + 3.0f * u2 + 3.0f * u1 + 1.0f) * fl;
            float v3 = u3 * fl;

            const int kb = i * 9 - klo;
            if ((unsigned)kb < 64u) {  // silu slot (j=0)
                uint32_t off = swAT(kb, r);
                sts16(ah + off, __half_as_ushort(__float2half_rn(f0)));
            }
            // window values at slot (bi mod 8); zero value if bi invalid
#pragma unroll
            for (int g = 0; g < 4; g++) {
                int bi = m - 3 + g;
                int slot = (bi + 8) & 7;
                int k = kb + 1 + slot;
                float v = (g == 0) ? v0 : (g == 1) ? v1 : (g == 2) ? v2 : v3;
                v = ((unsigned)bi <= 7u) ? v : 0.0f;
                if ((unsigned)k < 64u) {
                    uint32_t off = swAT(k, r);
                    sts16(ah + off, __half_as_ushort(__float2half_rn(v)));
                }
            }
            // complement slots get zero: (m+1..m+4) mod 8
#pragma unroll
            for (int t = 0; t < 4; t++) {
                int slot = (m + 1 + t) & 7;
                int k = kb + 1 + slot;
                if ((unsigned)k < 64u) {
                    uint32_t off = swAT(k, r);
                    sts16(ah + off, 0);
                }
            }
        }
        if (K < KPAD && c == NCHUNK - 1) {  // layer0 tail zero cols
            constexpr int PADC = 64 - (K & 63);  // 20 for K=108
            int base = 64 - PADC + (PADC / 2) * half_;
#pragma unroll
            for (int j = 0; j < PADC / 2; j++) {
                sts16(ah + swAT(base + j, r), 0);
            }
        }
    };

    auto mma_chunk = [&](int st) {
        const uint32_t A0 = sb + (uint32_t)st * ABUF;
        const uint32_t Bh = BBASE + (uint32_t)(st * 2) * BBUF;
        const uint32_t Bl = Bh + BBUF;
#pragma unroll
        for (int ks = 0; ks < 4; ks++) {
            uint32_t a[4];
            ldsm4t(A0 + a_sw + (uint32_t)(ks * 4096), a);
#pragma unroll
            for (int q = 0; q < NT2; q++) {
                uint32_t bo = sw128((uint32_t)((16 * q + brow) * 128 + bseg * 16 + ks * 32));
                uint32_t bh[4], bl[4];
                ldsm4(Bh + bo, bh);
                ldsm4(Bl + bo, bl);
                mma16816(acc[2 * q], a, bh[0], bh[1]);
                mma16816(acc[2 * q + 1], a, bh[2], bh[3]);
                mma16816(acc[2 * q], a, bl[0], bl[1]);
                mma16816(acc[2 * q + 1], a, bl[2], bl[3]);
            }
            if constexpr (NT & 1) {
                uint32_t bo = sw128((uint32_t)((8 * (NT - 1) + (lane & 7)) * 128 +
                                               ((lane >> 3) & 1) * 16 + ks * 32));
                uint32_t bh2[2], bl2[2];
                ldsm2(Bh + bo, bh2);
                ldsm2(Bl + bo, bl2);
                mma16816(acc[NT - 1], a, bh2[0], bh2[1]);
                mma16816(acc[NT - 1], a, bl2[0], bl2[1]);
            }
        }
    };

    // ---------------- main pipeline ----------------
    float xb0[5], xb1[5];
    prefetch(0, xb0);
    if (NCHUNK > 1) prefetch(1, xb1);
    stageB(0, 0);
    scatter(0, 0, xb0);
    cp_wait0();
    __syncthreads();

    for (int c = 0; c < NCHUNK; c++) {
        const int st = c & 1;
        if (c + 2 < NCHUNK) prefetch(c + 2, (c & 1) ? xb1 : xb0);
        if (c + 1 < NCHUNK) stageB(c + 1, st ^ 1);
        mma_chunk(st);
        if (c + 1 < NCHUNK) scatter(c + 1, st ^ 1, ((c + 1) & 1) ? xb1 : xb0);
        cp_wait0();
        __syncthreads();
    }

    // ---------------- epilogue: smem transpose -> coalesced STG ----------------
    constexpr int SP = 132;
    float* S = reinterpret_cast<float*>(dsm);  // reuse A region
    __syncthreads();
    {
        const int er0 = wid * 16 + (lane >> 2);
        const int er1 = er0 + 8;
#pragma unroll
        for (int p = 0; p < NT; p++) {
            int o = p * 8 + (lane & 3) * 2;
            S[o * SP + er0] = acc[p][0];
            S[(o + 1) * SP + er0] = acc[p][1];
            S[o * SP + er1] = acc[p][2];
            S[(o + 1) * SP + er1] = acc[p][3];
        }
    }
    __syncthreads();
    for (int idx = tid; idx < OUT * 128; idx += 256) {
        int o = idx >> 7;
        int rr = idx & 127;
        float val = S[o * SP + rr];
        if (OUT_NCHW) hout[((row0 >> 12) * OUT + o) * 4096 + (row0 & 4095) + rr] = val;
        else hout[o * N + row0 + rr] = val;
    }
}

// ------------------------------- launch ------------------------------------

extern "C" void kernel_launch(void* const* d_in, const int* in_sizes, int n_in,
                              void* d_out, int out_size) {
    const float* x     = (const float*)d_in[0];
    const float* grid0 = (const float*)d_in[1];
    const float* coef0 = (const float*)d_in[2];
    const float* sb0   = (const float*)d_in[3];
    const float* ss0   = (const float*)d_in[4];
    const float* grid1 = (const float*)d_in[5];
    const float* coef1 = (const float*)d_in[6];
    const float* sb1   = (const float*)d_in[7];
    const float* ss1   = (const float*)d_in[8];
    const float* grid2 = (const float*)d_in[9];
    const float* coef2 = (const float*)d_in[10];
    const float* sb2   = (const float*)d_in[11];
    const float* ss2   = (const float*)d_in[12];
    float* out = (float*)d_out;

    int N = in_sizes[0] / 12;
    if (N > MAXN) N = MAXN;

    float *h1, *h2;
    __half *Whi0, *Wlo0, *Whi1, *Wlo1, *Whi2, *Wlo2;
    cudaGetSymbolAddress((void**)&h1, g_h1);
    cudaGetSymbolAddress((void**)&h2, g_h2);
    cudaGetSymbolAddress((void**)&Whi0, g_Whi0);
    cudaGetSymbolAddress((void**)&Wlo0, g_Wlo0);
    cudaGetSymbolAddress((void**)&Whi1, g_Whi1);
    cudaGetSymbolAddress((void**)&Wlo1, g_Wlo1);
    cudaGetSymbolAddress((void**)&Whi2, g_Whi2);
    cudaGetSymbolAddress((void**)&Wlo2, g_Wlo2);

    constexpr int FOLD_TOTAL = 64 * 128 + 64 * 576 + 24 * 576;
    fold_all<<<(FOLD_TOTAL + 255) / 256, 256>>>(coef0, sb0, ss0, coef1, sb1, ss1,
                                                coef2, sb2, ss2, Whi0, Wlo0,
                                                Whi1, Wlo1, Whi2, Wlo2);

    auto k0 = kan_mma<12, 64, 108, 128, 2, true, false>;
    auto k1 = kan_mma<64, 64, 576, 576, 9, false, false>;
    auto k2 = kan_mma<64, 24, 576, 576, 9, false, true>;

    constexpr int SM01 = 2 * 64 * 256 + 4 * 64 * 128;  // 65536
    constexpr int SM2  = 2 * 64 * 256 + 4 * 24 * 128;  // 45056
    cudaFuncSetAttribute(k0, cudaFuncAttributeMaxDynamicSharedMemorySize, SM01);
    cudaFuncSetAttribute(k1, cudaFuncAttributeMaxDynamicSharedMemorySize, SM01);
    cudaFuncSetAttribute(k2, cudaFuncAttributeMaxDynamicSharedMemorySize, SM2);

    int blocks = N / 128;
    k0<<<blocks, 256, SM01>>>(x, grid0, Whi0, Wlo0, h1, N);
    k1<<<blocks, 256, SM01>>>(h1, grid1, Whi1, Wlo1, h2, N);
    k2<<<blocks, 256, SM2>>>(h2, grid2, Whi2, Wlo2, out, N);
}

// round 12
// speedup vs baseline: 1.5819x; 1.1457x over previous
#include <cuda_runtime.h>
#include <cuda_fp16.h>
#include <cstdint>

// ---------------------------------------------------------------------------
// KAN 3-layer (12->64->64->24) via warp mma.sync fp16 2-pass (A single fp16,
// B split fp16 hi/lo). Chunk = 72 cols = 8 whole inputs (no straddlers, no
// bounds predicates, compile-time kb). A K-major pitch 272B, B pitch 176B
// (padded strides, no XOR swizzle). MMA runs 5 k-steps (pad cols pre-zeroed).
// ---------------------------------------------------------------------------

#define MAXN (32 * 64 * 64)

__device__ float g_h1[64 * MAXN];
__device__ float g_h2[64 * MAXN];
__device__ __align__(16) __half g_Whi0[64 * 144];
__device__ __align__(16) __half g_Wlo0[64 * 144];
__device__ __align__(16) __half g_Whi1[64 * 576];
__device__ __align__(16) __half g_Wlo1[64 * 576];
__device__ __align__(16) __half g_Whi2[24 * 576];
__device__ __align__(16) __half g_Wlo2[24 * 576];

// ------------------------------- helpers -----------------------------------

__device__ __forceinline__ uint32_t smem_u32(const void* p) {
    uint32_t a;
    asm("{ .reg .u64 t; cvta.to.shared.u64 t, %1; cvt.u32.u64 %0, t; }"
        : "=r"(a) : "l"(p));
    return a;
}
__device__ __forceinline__ void ldsm4(uint32_t addr, uint32_t r[4]) {
    asm volatile("ldmatrix.sync.aligned.m8n8.x4.shared.b16 {%0,%1,%2,%3}, [%4];"
                 : "=r"(r[0]), "=r"(r[1]), "=r"(r[2]), "=r"(r[3]) : "r"(addr));
}
__device__ __forceinline__ void ldsm4t(uint32_t addr, uint32_t r[4]) {
    asm volatile("ldmatrix.sync.aligned.m8n8.x4.trans.shared.b16 {%0,%1,%2,%3}, [%4];"
                 : "=r"(r[0]), "=r"(r[1]), "=r"(r[2]), "=r"(r[3]) : "r"(addr));
}
__device__ __forceinline__ void ldsm2(uint32_t addr, uint32_t r[2]) {
    asm volatile("ldmatrix.sync.aligned.m8n8.x2.shared.b16 {%0,%1}, [%2];"
                 : "=r"(r[0]), "=r"(r[1]) : "r"(addr));
}
__device__ __forceinline__ void mma16816(float c[4], const uint32_t a[4],
                                         uint32_t b0, uint32_t b1) {
    asm volatile(
        "mma.sync.aligned.m16n8k16.row.col.f32.f16.f16.f32 "
        "{%0,%1,%2,%3},{%4,%5,%6,%7},{%8,%9},{%0,%1,%2,%3};"
        : "+f"(c[0]), "+f"(c[1]), "+f"(c[2]), "+f"(c[3])
        : "r"(a[0]), "r"(a[1]), "r"(a[2]), "r"(a[3]), "r"(b0), "r"(b1));
}
__device__ __forceinline__ void sts16(uint32_t addr, unsigned short v) {
    asm volatile("st.shared.b16 [%0], %1;" :: "r"(addr), "h"(v));
}
__device__ __forceinline__ void sts128z(uint32_t addr) {
    asm volatile("st.shared.v4.b32 [%0], {%1,%1,%1,%1};" :: "r"(addr), "r"(0u));
}
__device__ __forceinline__ void cp16(uint32_t dst, const void* src) {
    asm volatile("cp.async.ca.shared.global [%0], [%1], 16;"
                 :: "r"(dst), "l"(src) : "memory");
}
__device__ __forceinline__ void cp_commit() {
    asm volatile("cp.async.commit_group;" ::: "memory");
}
__device__ __forceinline__ void cp_wait0() {
    asm volatile("cp.async.wait_group 0;" ::: "memory");
}

// ------------------------------- fold kernel (fused, all 3 layers) ---------
__global__ void fold_all(const float* c0, const float* b0, const float* s0,
                         const float* c1, const float* b1, const float* s1,
                         const float* c2, const float* b2, const float* s2,
                         __half* Whi0, __half* Wlo0,
                         __half* Whi1, __half* Wlo1,
                         __half* Whi2, __half* Wlo2) {
    int idx = blockIdx.x * blockDim.x + threadIdx.x;
    const float *coef, *sbp, *ss;
    __half *Whi, *Wlo;
    int IN, OUT, KPAD;
    if (idx < 64 * 144) {
        coef = c0; sbp = b0; ss = s0; Whi = Whi0; Wlo = Wlo0;
        IN = 12; OUT = 64; KPAD = 144;
    } else if (idx < 64 * 144 + 64 * 576) {
        idx -= 64 * 144;
        coef = c1; sbp = b1; ss = s1; Whi = Whi1; Wlo = Wlo1;
        IN = 64; OUT = 64; KPAD = 576;
    } else if (idx < 64 * 144 + 64 * 576 + 24 * 576) {
        idx -= 64 * 144 + 64 * 576;
        coef = c2; sbp = b2; ss = s2; Whi = Whi2; Wlo = Wlo2;
        IN = 64; OUT = 24; KPAD = 576;
    } else return;
    int o = idx / KPAD, k = idx % KPAD;
    float w = 0.0f;
    if (k < IN * 9) {
        int i = k / 9, j = k % 9;
        w = (j == 0) ? sbp[i * OUT + o] : coef[(i * OUT + o) * 8 + (j - 1)] * ss[i * OUT + o];
    }
    __half hi = __float2half_rn(w);
    __half lo = __float2half_rn(w - __half2float(hi));
    Whi[idx] = hi;
    Wlo[idx] = lo;
}

// ------------------------------- layer kernel ------------------------------
// SMEM: A[stage] 80k x 272B = 21760B each (2 stages),
//       B[stage][hi/lo] OUT x 176B each (4 buffers).
template <int IN, int OUT, int K, int KPAD, int NCHUNK, bool IN_NCHW, bool OUT_NCHW>
__global__ void __launch_bounds__(256, 2)
kan_mma(const float* __restrict__ hin, const float* __restrict__ grid,
        const __half* __restrict__ Whi, const __half* __restrict__ Wlo,
        float* __restrict__ hout, int N) {
    constexpr int NT = OUT / 8;
    constexpr int NT2 = NT / 2;
    constexpr int APITCH = 272;
    constexpr int ABUF = 80 * APITCH;   // 21760
    constexpr int BPITCH = 176;
    constexpr int BBUF = OUT * BPITCH;
    constexpr int SMTOT = 2 * ABUF + 4 * BBUF;
    constexpr bool KFULL = (K % 72 == 0);

    extern __shared__ char dsm[];
    const uint32_t sb = smem_u32(dsm);
    const uint32_t BBASE = sb + 2 * ABUF;

    const int tid = threadIdx.x;
    const int wid = tid >> 5;
    const int lane = tid & 31;
    const int row0 = blockIdx.x * 128;

    const float t0 = __ldg(grid + 0);
    const float invh = 1.0f / (__ldg(grid + 1) - t0);
    const float t11 = __ldg(grid + 11);

    const int r = tid & 127;
    const int half_ = tid >> 7;
    const int rowg = row0 + r;
    const int img = rowg >> 12;
    const int pix = rowg & 4095;

    // fragment addressing
    const int gq = lane >> 3;
    const int a_k = (lane & 7) + ((gq >> 1) * 8);
    const int a_m = wid * 16 + (gq & 1) * 8;
    const uint32_t a_sw = (uint32_t)(a_k * APITCH + a_m * 2);  // +ks*16*APITCH
    const int brow = (lane & 7) + 8 * (gq >> 1);
    const int bseg = gq & 1;

    float acc[NT][4];
#pragma unroll
    for (int p = 0; p < NT; p++)
#pragma unroll
        for (int q = 0; q < 4; q++) acc[p][q] = 0.0f;

    // ---------------- prologue: zero ALL smem (A pads, B pads, layer0 tail) --
    for (int z = tid * 16; z < SMTOT; z += 256 * 16) sts128z(sb + z);

    // ---------------- pipeline helpers ----------------
    auto prefetch = [&](int c, float* xr) {
#pragma unroll
        for (int j = 0; j < 4; j++) {
            int i = c * 8 + half_ * 4 + j;
            int idx;
            if (IN_NCHW) idx = (img * IN + i) * 4096 + pix;
            else idx = i * N + rowg;
            xr[j] = (i < IN) ? __ldg(hin + idx) : 0.0f;
        }
    };

    auto stageB = [&](int c, int st) {
        uint32_t bb = BBASE + (uint32_t)(st * 2) * BBUF;
        for (int v = tid; v < OUT * 18; v += 256) {
            int h = v >= OUT * 9;
            int u = v - (h ? OUT * 9 : 0);
            int o = u / 9, seg = u - o * 9;
            const __half* src = (h ? Wlo : Whi) + o * KPAD + c * 72 + seg * 8;
            cp16(bb + (uint32_t)h * BBUF + (uint32_t)(o * BPITCH + seg * 16), src);
        }
        cp_commit();
    };

    auto scatter = [&](int c, int st, const float* xr) {
        const uint32_t ah = sb + (uint32_t)st * ABUF + (uint32_t)(r * 2) +
                            (uint32_t)(half_ * 36 * APITCH);
#pragma unroll
        for (int j = 0; j < 4; j++) {
            int i = c * 8 + half_ * 4 + j;
            if (IN < 64 && i >= IN) break;  // layer0 tail only
            float x = xr[j];
            float f0 = __fdividef(x, 1.0f + __expf(-x));  // silu

            bool inr = (x >= t0) && (x < t11);
            float s = (x - t0) * invh;
            s = fminf(fmaxf(s, 0.0f), 10.999f);
            int m = (int)s;
            float u1 = s - (float)m;
            float um = 1.0f - u1;
            float u2 = u1 * u1, u3 = u2 * u1;
            float fl = inr ? (1.0f / 6.0f) : 0.0f;
            float v0 = um * um * um * fl;
            float v1 = (3.0f * u3 - 6.0f * u2 + 4.0f) * fl;
            float v2 = (-3.0f * u3 + 3.0f * u2 + 3.0f * u1 + 1.0f) * fl;
            float v3 = u3 * fl;

            const uint32_t abase = ah + (uint32_t)(9 * j * APITCH);  // compile-time per j
            // silu slot (chunk-local col kb)
            sts16(abase, __half_as_ushort(__float2half_rn(f0)));
            // window values at slot (bi mod 8) -> col kb+1+slot (always in-range)
#pragma unroll
            for (int g = 0; g < 4; g++) {
                int bi = m - 3 + g;
                int slot = (bi + 8) & 7;
                float v = (g == 0) ? v0 : (g == 1) ? v1 : (g == 2) ? v2 : v3;
                v = ((unsigned)bi <= 7u) ? v : 0.0f;
                sts16(abase + (uint32_t)((1 + slot) * APITCH),
                      __half_as_ushort(__float2half_rn(v)));
            }
            // complement slots zero: (m+1..m+4) mod 8
#pragma unroll
            for (int t = 0; t < 4; t++) {
                int slot = (m + 1 + t) & 7;
                sts16(abase + (uint32_t)((1 + slot) * APITCH), 0);
            }
        }
    };

    auto mma_chunk = [&](int c, int st) {
        const uint32_t A0 = sb + (uint32_t)st * ABUF;
        const uint32_t Bh = BBASE + (uint32_t)(st * 2) * BBUF;
        const uint32_t Bl = Bh + BBUF;
        const int ksn = KFULL ? 5 : ((K - c * 72 + 15) >> 4 < 5 ? (K - c * 72 + 15) >> 4 : 5);
#pragma unroll
        for (int ks = 0; ks < 5; ks++) {
            if (!KFULL && ks >= ksn) break;
            uint32_t a[4];
            ldsm4t(A0 + a_sw + (uint32_t)(ks * 16 * APITCH), a);
#pragma unroll
            for (int q = 0; q < NT2; q++) {
                uint32_t bo = (uint32_t)((16 * q + brow) * BPITCH + bseg * 16 + ks * 32);
                uint32_t bh[4], bl[4];
                ldsm4(Bh + bo, bh);
                ldsm4(Bl + bo, bl);
                mma16816(acc[2 * q], a, bh[0], bh[1]);
                mma16816(acc[2 * q + 1], a, bh[2], bh[3]);
                mma16816(acc[2 * q], a, bl[0], bl[1]);
                mma16816(acc[2 * q + 1], a, bl[2], bl[3]);
            }
            if constexpr (NT & 1) {
                uint32_t bo = (uint32_t)((8 * (NT - 1) + (lane & 7)) * BPITCH +
                                         ((lane >> 3) & 1) * 16 + ks * 32);
                uint32_t bh2[2], bl2[2];
                ldsm2(Bh + bo, bh2);
                ldsm2(Bl + bo, bl2);
                mma16816(acc[NT - 1], a, bh2[0], bh2[1]);
                mma16816(acc[NT - 1], a, bl2[0], bl2[1]);
            }
        }
    };

    // ---------------- main pipeline ----------------
    float xb0[4], xb1[4];
    prefetch(0, xb0);
    if (NCHUNK > 1) prefetch(1, xb1);
    __syncthreads();  // prologue zero visible before scatter
    stageB(0, 0);
    scatter(0, 0, xb0);
    cp_wait0();
    __syncthreads();

    for (int c = 0; c < NCHUNK; c++) {
        const int st = c & 1;
        if (c + 2 < NCHUNK) prefetch(c + 2, (c & 1) ? xb1 : xb0);
        if (c + 1 < NCHUNK) stageB(c + 1, st ^ 1);
        mma_chunk(c, st);
        if (c + 1 < NCHUNK) scatter(c + 1, st ^ 1, ((c + 1) & 1) ? xb1 : xb0);
        cp_wait0();
        __syncthreads();
    }

    // ---------------- epilogue: smem transpose -> coalesced STG ----------------
    constexpr int SP = 132;
    float* S = reinterpret_cast<float*>(dsm);  // reuse A region
    __syncthreads();
    {
        const int er0 = wid * 16 + (lane >> 2);
        const int er1 = er0 + 8;
#pragma unroll
        for (int p = 0; p < NT; p++) {
            int o = p * 8 + (lane & 3) * 2;
            S[o * SP + er0] = acc[p][0];
            S[(o + 1) * SP + er0] = acc[p][1];
            S[o * SP + er1] = acc[p][2];
            S[(o + 1) * SP + er1] = acc[p][3];
        }
    }
    __syncthreads();
    for (int idx = tid; idx < OUT * 128; idx += 256) {
        int o = idx >> 7;
        int rr = idx & 127;
        float val = S[o * SP + rr];
        if (OUT_NCHW) hout[((row0 >> 12) * OUT + o) * 4096 + (row0 & 4095) + rr] = val;
        else hout[o * N + row0 + rr] = val;
    }
}

// ------------------------------- launch ------------------------------------

extern "C" void kernel_launch(void* const* d_in, const int* in_sizes, int n_in,
                              void* d_out, int out_size) {
    const float* x     = (const float*)d_in[0];
    const float* grid0 = (const float*)d_in[1];
    const float* coef0 = (const float*)d_in[2];
    const float* sb0   = (const float*)d_in[3];
    const float* ss0   = (const float*)d_in[4];
    const float* grid1 = (const float*)d_in[5];
    const float* coef1 = (const float*)d_in[6];
    const float* sb1   = (const float*)d_in[7];
    const float* ss1   = (const float*)d_in[8];
    const float* grid2 = (const float*)d_in[9];
    const float* coef2 = (const float*)d_in[10];
    const float* sb2   = (const float*)d_in[11];
    const float* ss2   = (const float*)d_in[12];
    float* out = (float*)d_out;

    int N = in_sizes[0] / 12;
    if (N > MAXN) N = MAXN;

    float *h1, *h2;
    __half *Whi0, *Wlo0, *Whi1, *Wlo1, *Whi2, *Wlo2;
    cudaGetSymbolAddress((void**)&h1, g_h1);
    cudaGetSymbolAddress((void**)&h2, g_h2);
    cudaGetSymbolAddress((void**)&Whi0, g_Whi0);
    cudaGetSymbolAddress((void**)&Wlo0, g_Wlo0);
    cudaGetSymbolAddress((void**)&Whi1, g_Whi1);
    cudaGetSymbolAddress((void**)&Wlo1, g_Wlo1);
    cudaGetSymbolAddress((void**)&Whi2, g_Whi2);
    cudaGetSymbolAddress((void**)&Wlo2, g_Wlo2);

    constexpr int FOLD_TOTAL = 64 * 144 + 64 * 576 + 24 * 576;
    fold_all<<<(FOLD_TOTAL + 255) / 256, 256>>>(coef0, sb0, ss0, coef1, sb1, ss1,
                                                coef2, sb2, ss2, Whi0, Wlo0,
                                                Whi1, Wlo1, Whi2, Wlo2);

    auto k0 = kan_mma<12, 64, 108, 144, 2, true, false>;
    auto k1 = kan_mma<64, 64, 576, 576, 8, false, false>;
    auto k2 = kan_mma<64, 24, 576, 576, 8, false, true>;

    constexpr int SM01 = 2 * 80 * 272 + 4 * 64 * 176;  // 88576
    constexpr int SM2  = 2 * 80 * 272 + 4 * 24 * 176;  // 60416
    cudaFuncSetAttribute(k0, cudaFuncAttributeMaxDynamicSharedMemorySize, SM01);
    cudaFuncSetAttribute(k1, cudaFuncAttributeMaxDynamicSharedMemorySize, SM01);
    cudaFuncSetAttribute(k2, cudaFuncAttributeMaxDynamicSharedMemorySize, SM2);

    int blocks = N / 128;
    k0<<<blocks, 256, SM01>>>(x, grid0, Whi0, Wlo0, h1, N);
    k1<<<blocks, 256, SM01>>>(h1, grid1, Whi1, Wlo1, h2, N);
    k2<<<blocks, 256, SM2>>>(h2, grid2, Whi2, Wlo2, out, N);
}

// round 13
// speedup vs baseline: 2.0687x; 1.3077x over previous
#include <cuda_runtime.h>
#include <cuda_fp16.h>
#include <cstdint>

// ---------------------------------------------------------------------------
// KAN 3-layer (12->64->64->24) via warp mma.sync fp16 SINGLE-pass (A and B
// both fp16). Chunk = 72 cols = 8 whole inputs. A K-major pitch 272B,
// B pitch 176B (padded strides, conflict-free, no XOR swizzle).
// ---------------------------------------------------------------------------

#define MAXN (32 * 64 * 64)

__device__ float g_h1[64 * MAXN];
__device__ float g_h2[64 * MAXN];
__device__ __align__(16) __half g_W0[64 * 144];
__device__ __align__(16) __half g_W1[64 * 576];
__device__ __align__(16) __half g_W2[24 * 576];

// ------------------------------- helpers -----------------------------------

__device__ __forceinline__ uint32_t smem_u32(const void* p) {
    uint32_t a;
    asm("{ .reg .u64 t; cvta.to.shared.u64 t, %1; cvt.u32.u64 %0, t; }"
        : "=r"(a) : "l"(p));
    return a;
}
__device__ __forceinline__ void ldsm4(uint32_t addr, uint32_t r[4]) {
    asm volatile("ldmatrix.sync.aligned.m8n8.x4.shared.b16 {%0,%1,%2,%3}, [%4];"
                 : "=r"(r[0]), "=r"(r[1]), "=r"(r[2]), "=r"(r[3]) : "r"(addr));
}
__device__ __forceinline__ void ldsm4t(uint32_t addr, uint32_t r[4]) {
    asm volatile("ldmatrix.sync.aligned.m8n8.x4.trans.shared.b16 {%0,%1,%2,%3}, [%4];"
                 : "=r"(r[0]), "=r"(r[1]), "=r"(r[2]), "=r"(r[3]) : "r"(addr));
}
__device__ __forceinline__ void ldsm2(uint32_t addr, uint32_t r[2]) {
    asm volatile("ldmatrix.sync.aligned.m8n8.x2.shared.b16 {%0,%1}, [%2];"
                 : "=r"(r[0]), "=r"(r[1]) : "r"(addr));
}
__device__ __forceinline__ void mma16816(float c[4], const uint32_t a[4],
                                         uint32_t b0, uint32_t b1) {
    asm volatile(
        "mma.sync.aligned.m16n8k16.row.col.f32.f16.f16.f32 "
        "{%0,%1,%2,%3},{%4,%5,%6,%7},{%8,%9},{%0,%1,%2,%3};"
        : "+f"(c[0]), "+f"(c[1]), "+f"(c[2]), "+f"(c[3])
        : "r"(a[0]), "r"(a[1]), "r"(a[2]), "r"(a[3]), "r"(b0), "r"(b1));
}
__device__ __forceinline__ void sts16(uint32_t addr, unsigned short v) {
    asm volatile("st.shared.b16 [%0], %1;" :: "r"(addr), "h"(v));
}
__device__ __forceinline__ void sts128z(uint32_t addr) {
    asm volatile("st.shared.v4.b32 [%0], {%1,%1,%1,%1};" :: "r"(addr), "r"(0u));
}
__device__ __forceinline__ void cp16(uint32_t dst, const void* src) {
    asm volatile("cp.async.ca.shared.global [%0], [%1], 16;"
                 :: "r"(dst), "l"(src) : "memory");
}
__device__ __forceinline__ void cp_commit() {
    asm volatile("cp.async.commit_group;" ::: "memory");
}
__device__ __forceinline__ void cp_wait0() {
    asm volatile("cp.async.wait_group 0;" ::: "memory");
}

// ------------------------------- fold kernel (fused, all 3 layers) ---------
__global__ void fold_all(const float* c0, const float* b0, const float* s0,
                         const float* c1, const float* b1, const float* s1,
                         const float* c2, const float* b2, const float* s2,
                         __half* W0, __half* W1, __half* W2) {
    int idx = blockIdx.x * blockDim.x + threadIdx.x;
    const float *coef, *sbp, *ss;
    __half* W;
    int IN, OUT, KPAD;
    if (idx < 64 * 144) {
        coef = c0; sbp = b0; ss = s0; W = W0;
        IN = 12; OUT = 64; KPAD = 144;
    } else if (idx < 64 * 144 + 64 * 576) {
        idx -= 64 * 144;
        coef = c1; sbp = b1; ss = s1; W = W1;
        IN = 64; OUT = 64; KPAD = 576;
    } else if (idx < 64 * 144 + 64 * 576 + 24 * 576) {
        idx -= 64 * 144 + 64 * 576;
        coef = c2; sbp = b2; ss = s2; W = W2;
        IN = 64; OUT = 24; KPAD = 576;
    } else return;
    int o = idx / KPAD, k = idx % KPAD;
    float w = 0.0f;
    if (k < IN * 9) {
        int i = k / 9, j = k % 9;
        w = (j == 0) ? sbp[i * OUT + o] : coef[(i * OUT + o) * 8 + (j - 1)] * ss[i * OUT + o];
    }
    W[idx] = __float2half_rn(w);
}

// ------------------------------- layer kernel ------------------------------
// SMEM: A[stage] 80k x 272B = 21760B each (2 stages),
//       B[stage] OUT x 176B each (2 buffers, single fp16).
template <int IN, int OUT, int K, int KPAD, int NCHUNK, bool IN_NCHW, bool OUT_NCHW>
__global__ void __launch_bounds__(256, 3)
kan_mma(const float* __restrict__ hin, const float* __restrict__ grid,
        const __half* __restrict__ W, float* __restrict__ hout, int N) {
    constexpr int NT = OUT / 8;
    constexpr int NT2 = NT / 2;
    constexpr int APITCH = 272;
    constexpr int ABUF = 80 * APITCH;   // 21760
    constexpr int BPITCH = 176;
    constexpr int BBUF = OUT * BPITCH;
    constexpr int SMTOT = 2 * ABUF + 2 * BBUF;
    constexpr bool KFULL = (K % 72 == 0);

    extern __shared__ char dsm[];
    const uint32_t sb = smem_u32(dsm);
    const uint32_t BBASE = sb + 2 * ABUF;

    const int tid = threadIdx.x;
    const int wid = tid >> 5;
    const int lane = tid & 31;
    const int row0 = blockIdx.x * 128;

    const float t0 = __ldg(grid + 0);
    const float invh = 1.0f / (__ldg(grid + 1) - t0);
    const float t11 = __ldg(grid + 11);

    const int r = tid & 127;
    const int half_ = tid >> 7;
    const int rowg = row0 + r;
    const int img = rowg >> 12;
    const int pix = rowg & 4095;

    // fragment addressing
    const int gq = lane >> 3;
    const int a_k = (lane & 7) + ((gq >> 1) * 8);
    const int a_m = wid * 16 + (gq & 1) * 8;
    const uint32_t a_sw = (uint32_t)(a_k * APITCH + a_m * 2);  // +ks*16*APITCH
    const int brow = (lane & 7) + 8 * (gq >> 1);
    const int bseg = gq & 1;

    float acc[NT][4];
#pragma unroll
    for (int p = 0; p < NT; p++)
#pragma unroll
        for (int q = 0; q < 4; q++) acc[p][q] = 0.0f;

    // ---------------- prologue: zero ALL smem (A pads, B pads, layer0 tail) --
    for (int z = tid * 16; z < SMTOT; z += 256 * 16) sts128z(sb + z);

    // ---------------- pipeline helpers ----------------
    auto prefetch = [&](int c, float* xr) {
#pragma unroll
        for (int j = 0; j < 4; j++) {
            int i = c * 8 + half_ * 4 + j;
            int idx;
            if (IN_NCHW) idx = (img * IN + i) * 4096 + pix;
            else idx = i * N + rowg;
            xr[j] = (i < IN) ? __ldg(hin + idx) : 0.0f;
        }
    };

    auto stageB = [&](int c, int st) {
        uint32_t bb = BBASE + (uint32_t)st * BBUF;
        for (int v = tid; v < OUT * 9; v += 256) {
            int o = v / 9, seg = v - o * 9;
            const __half* src = W + o * KPAD + c * 72 + seg * 8;
            cp16(bb + (uint32_t)(o * BPITCH + seg * 16), src);
        }
        cp_commit();
    };

    auto scatter = [&](int c, int st, const float* xr) {
        const uint32_t ah = sb + (uint32_t)st * ABUF + (uint32_t)(r * 2) +
                            (uint32_t)(half_ * 36 * APITCH);
#pragma unroll
        for (int j = 0; j < 4; j++) {
            int i = c * 8 + half_ * 4 + j;
            if (IN < 64 && i >= IN) break;  // layer0 tail only
            float x = xr[j];
            float f0 = __fdividef(x, 1.0f + __expf(-x));  // silu

            bool inr = (x >= t0) && (x < t11);
            float s = (x - t0) * invh;
            s = fminf(fmaxf(s, 0.0f), 10.999f);
            int m = (int)s;
            float u1 = s - (float)m;
            float um = 1.0f - u1;
            float u2 = u1 * u1, u3 = u2 * u1;
            float fl = inr ? (1.0f / 6.0f) : 0.0f;
            float v0 = um * um * um * fl;
            float v1 = (3.0f * u3 - 6.0f * u2 + 4.0f) * fl;
            float v2 = (-3.0f * u3 + 3.0f * u2 + 3.0f * u1 + 1.0f) * fl;
            float v3 = u3 * fl;

            const uint32_t abase = ah + (uint32_t)(9 * j * APITCH);
            // silu slot (chunk-local col kb)
            sts16(abase, __half_as_ushort(__float2half_rn(f0)));
            // window values at slot (bi mod 8) -> col kb+1+slot
#pragma unroll
            for (int g = 0; g < 4; g++) {
                int bi = m - 3 + g;
                int slot = (bi + 8) & 7;
                float v = (g == 0) ? v0 : (g == 1) ? v1 : (g == 2) ? v2 : v3;
                v = ((unsigned)bi <= 7u) ? v : 0.0f;
                sts16(abase + (uint32_t)((1 + slot) * APITCH),
                      __half_as_ushort(__float2half_rn(v)));
            }
            // complement slots zero: (m+1..m+4) mod 8
#pragma unroll
            for (int t = 0; t < 4; t++) {
                int slot = (m + 1 + t) & 7;
                sts16(abase + (uint32_t)((1 + slot) * APITCH), 0);
            }
        }
    };

    auto mma_chunk = [&](int c, int st) {
        const uint32_t A0 = sb + (uint32_t)st * ABUF;
        const uint32_t Bh = BBASE + (uint32_t)st * BBUF;
        const int ksn = KFULL ? 5 : ((K - c * 72 + 15) >> 4 < 5 ? (K - c * 72 + 15) >> 4 : 5);
#pragma unroll
        for (int ks = 0; ks < 5; ks++) {
            if (!KFULL && ks >= ksn) break;
            uint32_t a[4];
            ldsm4t(A0 + a_sw + (uint32_t)(ks * 16 * APITCH), a);
#pragma unroll
            for (int q = 0; q < NT2; q++) {
                uint32_t bo = (uint32_t)((16 * q + brow) * BPITCH + bseg * 16 + ks * 32);
                uint32_t bh[4];
                ldsm4(Bh + bo, bh);
                mma16816(acc[2 * q], a, bh[0], bh[1]);
                mma16816(acc[2 * q + 1], a, bh[2], bh[3]);
            }
            if constexpr (NT & 1) {
                uint32_t bo = (uint32_t)((8 * (NT - 1) + (lane & 7)) * BPITCH +
                                         ((lane >> 3) & 1) * 16 + ks * 32);
                uint32_t bh2[2];
                ldsm2(Bh + bo, bh2);
                mma16816(acc[NT - 1], a, bh2[0], bh2[1]);
            }
        }
    };

    // ---------------- main pipeline ----------------
    float xb0[4], xb1[4];
    prefetch(0, xb0);
    if (NCHUNK > 1) prefetch(1, xb1);
    __syncthreads();  // prologue zero visible before scatter
    stageB(0, 0);
    scatter(0, 0, xb0);
    cp_wait0();
    __syncthreads();

    for (int c = 0; c < NCHUNK; c++) {
        const int st = c & 1;
        if (c + 2 < NCHUNK) prefetch(c + 2, (c & 1) ? xb1 : xb0);
        if (c + 1 < NCHUNK) stageB(c + 1, st ^ 1);
        mma_chunk(c, st);
        if (c + 1 < NCHUNK) scatter(c + 1, st ^ 1, ((c + 1) & 1) ? xb1 : xb0);
        cp_wait0();
        __syncthreads();
    }

    // ---------------- epilogue: smem transpose -> coalesced STG ----------------
    constexpr int SP = 132;
    float* S = reinterpret_cast<float*>(dsm);  // reuse A region
    __syncthreads();
    {
        const int er0 = wid * 16 + (lane >> 2);
        const int er1 = er0 + 8;
#pragma unroll
        for (int p = 0; p < NT; p++) {
            int o = p * 8 + (lane & 3) * 2;
            S[o * SP + er0] = acc[p][0];
            S[(o + 1) * SP + er0] = acc[p][1];
            S[o * SP + er1] = acc[p][2];
            S[(o + 1) * SP + er1] = acc[p][3];
        }
    }
    __syncthreads();
    for (int idx = tid; idx < OUT * 128; idx += 256) {
        int o = idx >> 7;
        int rr = idx & 127;
        float val = S[o * SP + rr];
        if (OUT_NCHW) hout[((row0 >> 12) * OUT + o) * 4096 + (row0 & 4095) + rr] = val;
        else hout[o * N + row0 + rr] = val;
    }
}

// ------------------------------- launch ------------------------------------

extern "C" void kernel_launch(void* const* d_in, const int* in_sizes, int n_in,
                              void* d_out, int out_size) {
    const float* x     = (const float*)d_in[0];
    const float* grid0 = (const float*)d_in[1];
    const float* coef0 = (const float*)d_in[2];
    const float* sb0   = (const float*)d_in[3];
    const float* ss0   = (const float*)d_in[4];
    const float* grid1 = (const float*)d_in[5];
    const float* coef1 = (const float*)d_in[6];
    const float* sb1   = (const float*)d_in[7];
    const float* ss1   = (const float*)d_in[8];
    const float* grid2 = (const float*)d_in[9];
    const float* coef2 = (const float*)d_in[10];
    const float* sb2   = (const float*)d_in[11];
    const float* ss2   = (const float*)d_in[12];
    float* out = (float*)d_out;

    int N = in_sizes[0] / 12;
    if (N > MAXN) N = MAXN;

    float *h1, *h2;
    __half *W0, *W1, *W2;
    cudaGetSymbolAddress((void**)&h1, g_h1);
    cudaGetSymbolAddress((void**)&h2, g_h2);
    cudaGetSymbolAddress((void**)&W0, g_W0);
    cudaGetSymbolAddress((void**)&W1, g_W1);
    cudaGetSymbolAddress((void**)&W2, g_W2);

    constexpr int FOLD_TOTAL = 64 * 144 + 64 * 576 + 24 * 576;
    fold_all<<<(FOLD_TOTAL + 255) / 256, 256>>>(coef0, sb0, ss0, coef1, sb1, ss1,
                                                coef2, sb2, ss2, W0, W1, W2);

    auto k0 = kan_mma<12, 64, 108, 144, 2, true, false>;
    auto k1 = kan_mma<64, 64, 576, 576, 8, false, false>;
    auto k2 = kan_mma<64, 24, 576, 576, 8, false, true>;

    constexpr int SM01 = 2 * 80 * 272 + 2 * 64 * 176;  // 66048
    constexpr int SM2  = 2 * 80 * 272 + 2 * 24 * 176;  // 51968
    cudaFuncSetAttribute(k0, cudaFuncAttributeMaxDynamicSharedMemorySize, SM01);
    cudaFuncSetAttribute(k1, cudaFuncAttributeMaxDynamicSharedMemorySize, SM01);
    cudaFuncSetAttribute(k2, cudaFuncAttributeMaxDynamicSharedMemorySize, SM2);

    int blocks = N / 128;
    k0<<<blocks, 256, SM01>>>(x, grid0, W0, h1, N);
    k1<<<blocks, 256, SM01>>>(h1, grid1, W1, h2, N);
    k2<<<blocks, 256, SM2>>>(h2, grid2, W2, out, N);
}

// round 14
// speedup vs baseline: 2.1690x; 1.0485x over previous
#include <cuda_runtime.h>
#include <cuda_fp16.h>
#include <cstdint>

// ---------------------------------------------------------------------------
// KAN 3-layer (12->64->64->24) via warp mma.sync fp16 single-pass.
// Chunk = 72 cols = 8 whole inputs. A K-major pitch 272B, B pitch 176B.
// CSPLIT=2 warp tiling (4 row-groups x 2 col-groups) for OUT=64 layers to
// halve B ldsm duplication; layer2 runs CSPLIT=1 at 4 CTAs/SM.
// ---------------------------------------------------------------------------

#define MAXN (32 * 64 * 64)

__device__ float g_h1[64 * MAXN];
__device__ float g_h2[64 * MAXN];
__device__ __align__(16) __half g_W0[64 * 144];
__device__ __align__(16) __half g_W1[64 * 576];
__device__ __align__(16) __half g_W2[24 * 576];

// ------------------------------- helpers -----------------------------------

__device__ __forceinline__ uint32_t smem_u32(const void* p) {
    uint32_t a;
    asm("{ .reg .u64 t; cvta.to.shared.u64 t, %1; cvt.u32.u64 %0, t; }"
        : "=r"(a) : "l"(p));
    return a;
}
__device__ __forceinline__ void ldsm4(uint32_t addr, uint32_t r[4]) {
    asm volatile("ldmatrix.sync.aligned.m8n8.x4.shared.b16 {%0,%1,%2,%3}, [%4];"
                 : "=r"(r[0]), "=r"(r[1]), "=r"(r[2]), "=r"(r[3]) : "r"(addr));
}
__device__ __forceinline__ void ldsm4t(uint32_t addr, uint32_t r[4]) {
    asm volatile("ldmatrix.sync.aligned.m8n8.x4.trans.shared.b16 {%0,%1,%2,%3}, [%4];"
                 : "=r"(r[0]), "=r"(r[1]), "=r"(r[2]), "=r"(r[3]) : "r"(addr));
}
__device__ __forceinline__ void ldsm2(uint32_t addr, uint32_t r[2]) {
    asm volatile("ldmatrix.sync.aligned.m8n8.x2.shared.b16 {%0,%1}, [%2];"
                 : "=r"(r[0]), "=r"(r[1]) : "r"(addr));
}
__device__ __forceinline__ void mma16816(float c[4], const uint32_t a[4],
                                         uint32_t b0, uint32_t b1) {
    asm volatile(
        "mma.sync.aligned.m16n8k16.row.col.f32.f16.f16.f32 "
        "{%0,%1,%2,%3},{%4,%5,%6,%7},{%8,%9},{%0,%1,%2,%3};"
        : "+f"(c[0]), "+f"(c[1]), "+f"(c[2]), "+f"(c[3])
        : "r"(a[0]), "r"(a[1]), "r"(a[2]), "r"(a[3]), "r"(b0), "r"(b1));
}
__device__ __forceinline__ void sts16(uint32_t addr, unsigned short v) {
    asm volatile("st.shared.b16 [%0], %1;" :: "r"(addr), "h"(v));
}
__device__ __forceinline__ void sts128z(uint32_t addr) {
    asm volatile("st.shared.v4.b32 [%0], {%1,%1,%1,%1};" :: "r"(addr), "r"(0u));
}
__device__ __forceinline__ void cp16(uint32_t dst, const void* src) {
    asm volatile("cp.async.ca.shared.global [%0], [%1], 16;"
                 :: "r"(dst), "l"(src) : "memory");
}
__device__ __forceinline__ void cp_commit() {
    asm volatile("cp.async.commit_group;" ::: "memory");
}
__device__ __forceinline__ void cp_wait0() {
    asm volatile("cp.async.wait_group 0;" ::: "memory");
}

// ------------------------------- fold kernel (fused, all 3 layers) ---------
__global__ void fold_all(const float* c0, const float* b0, const float* s0,
                         const float* c1, const float* b1, const float* s1,
                         const float* c2, const float* b2, const float* s2,
                         __half* W0, __half* W1, __half* W2) {
    int idx = blockIdx.x * blockDim.x + threadIdx.x;
    const float *coef, *sbp, *ss;
    __half* W;
    int IN, OUT, KPAD;
    if (idx < 64 * 144) {
        coef = c0; sbp = b0; ss = s0; W = W0;
        IN = 12; OUT = 64; KPAD = 144;
    } else if (idx < 64 * 144 + 64 * 576) {
        idx -= 64 * 144;
        coef = c1; sbp = b1; ss = s1; W = W1;
        IN = 64; OUT = 64; KPAD = 576;
    } else if (idx < 64 * 144 + 64 * 576 + 24 * 576) {
        idx -= 64 * 144 + 64 * 576;
        coef = c2; sbp = b2; ss = s2; W = W2;
        IN = 64; OUT = 24; KPAD = 576;
    } else return;
    int o = idx / KPAD, k = idx % KPAD;
    float w = 0.0f;
    if (k < IN * 9) {
        int i = k / 9, j = k % 9;
        w = (j == 0) ? sbp[i * OUT + o] : coef[(i * OUT + o) * 8 + (j - 1)] * ss[i * OUT + o];
    }
    W[idx] = __float2half_rn(w);
}

// ------------------------------- layer kernel ------------------------------
// CSPLIT: warp tiling, 8/CSPLIT row-groups x CSPLIT col-groups.
template <int IN, int OUT, int K, int KPAD, int NCHUNK, bool IN_NCHW, bool OUT_NCHW,
          int CSPLIT, int MINB>
__global__ void __launch_bounds__(256, MINB)
kan_mma(const float* __restrict__ hin, const float* __restrict__ grid,
        const __half* __restrict__ W, float* __restrict__ hout, int N) {
    constexpr int MT = CSPLIT;             // m-tiles per warp
    constexpr int NTL = OUT / 8 / CSPLIT;  // n8-tiles per warp
    constexpr int NTL2 = NTL / 2;
    constexpr int OUTL = OUT / CSPLIT;
    constexpr int APITCH = 272;
    constexpr int ABUF = 80 * APITCH;
    constexpr int BPITCH = 176;
    constexpr int BBUF = OUT * BPITCH;
    constexpr int SMTOT = 2 * ABUF + 2 * BBUF;
    constexpr bool KFULL = (K % 72 == 0);

    extern __shared__ char dsm[];
    const uint32_t sb = smem_u32(dsm);
    const uint32_t BBASE = sb + 2 * ABUF;

    const int tid = threadIdx.x;
    const int wid = tid >> 5;
    const int lane = tid & 31;
    const int row0 = blockIdx.x * 128;

    const float t0 = __ldg(grid + 0);
    const float invh = 1.0f / (__ldg(grid + 1) - t0);
    const float t11 = __ldg(grid + 11);

    const int r = tid & 127;
    const int half_ = tid >> 7;
    const int rowg = row0 + r;
    const int img = rowg >> 12;
    const int pix = rowg & 4095;

    // warp tiling
    const int rg = wid / CSPLIT;
    const int cg = wid % CSPLIT;
    const int ob = cg * OUTL;

    // fragment addressing
    const int gq = lane >> 3;
    const int a_k = (lane & 7) + ((gq >> 1) * 8);
    uint32_t a_sw[MT];
#pragma unroll
    for (int mt = 0; mt < MT; mt++) {
        int a_m = rg * (16 * CSPLIT) + mt * 16 + (gq & 1) * 8;
        a_sw[mt] = (uint32_t)(a_k * APITCH + a_m * 2);
    }
    const int brow = (lane & 7) + 8 * (gq >> 1);
    const int bseg = gq & 1;

    float acc[MT][NTL][4];
#pragma unroll
    for (int mt = 0; mt < MT; mt++)
#pragma unroll
        for (int p = 0; p < NTL; p++)
#pragma unroll
            for (int q = 0; q < 4; q++) acc[mt][p][q] = 0.0f;

    // ---------------- prologue: zero ALL smem ----------------
    for (int z = tid * 16; z < SMTOT; z += 256 * 16) sts128z(sb + z);

    // ---------------- pipeline helpers ----------------
    auto prefetch = [&](int c, float* xr) {
#pragma unroll
        for (int j = 0; j < 4; j++) {
            int i = c * 8 + half_ * 4 + j;
            int idx;
            if (IN_NCHW) idx = (img * IN + i) * 4096 + pix;
            else idx = i * N + rowg;
            xr[j] = (i < IN) ? __ldg(hin + idx) : 0.0f;
        }
    };

    auto stageB = [&](int c, int st) {
        uint32_t bb = BBASE + (uint32_t)st * BBUF;
        for (int v = tid; v < OUT * 9; v += 256) {
            int o = v / 9, seg = v - o * 9;
            const __half* src = W + o * KPAD + c * 72 + seg * 8;
            cp16(bb + (uint32_t)(o * BPITCH + seg * 16), src);
        }
        cp_commit();
    };

    auto scatter = [&](int c, int st, const float* xr) {
        const uint32_t ah = sb + (uint32_t)st * ABUF + (uint32_t)(r * 2) +
                            (uint32_t)(half_ * 36 * APITCH);
#pragma unroll
        for (int j = 0; j < 4; j++) {
            int i = c * 8 + half_ * 4 + j;
            if (IN < 64 && i >= IN) break;  // layer0 tail only
            float x = xr[j];
            float f0 = __fdividef(x, 1.0f + __expf(-x));  // silu

            bool inr = (x >= t0) && (x < t11);
            float s = (x - t0) * invh;
            s = fminf(fmaxf(s, 0.0f), 10.999f);
            int m = (int)s;
            float u1 = s - (float)m;
            float um = 1.0f - u1;
            float u2 = u1 * u1, u3 = u2 * u1;
            float fl = inr ? (1.0f / 6.0f) : 0.0f;
            float v0 = um * um * um * fl;
            float v1 = (3.0f * u3 - 6.0f * u2 + 4.0f) * fl;
            float v2 = (-3.0f * u3 + 3.0f * u2 + 3.0f * u1 + 1.0f) * fl;
            float v3 = u3 * fl;

            const uint32_t abase = ah + (uint32_t)(9 * j * APITCH);
            sts16(abase, __half_as_ushort(__float2half_rn(f0)));
#pragma unroll
            for (int g = 0; g < 4; g++) {
                int bi = m - 3 + g;
                int slot = (bi + 8) & 7;
                float v = (g == 0) ? v0 : (g == 1) ? v1 : (g == 2) ? v2 : v3;
                v = ((unsigned)bi <= 7u) ? v : 0.0f;
                sts16(abase + (uint32_t)((1 + slot) * APITCH),
                      __half_as_ushort(__float2half_rn(v)));
            }
#pragma unroll
            for (int t = 0; t < 4; t++) {
                int slot = (m + 1 + t) & 7;
                sts16(abase + (uint32_t)((1 + slot) * APITCH), 0);
            }
        }
    };

    auto mma_chunk = [&](int c, int st) {
        const uint32_t A0 = sb + (uint32_t)st * ABUF;
        const uint32_t Bh = BBASE + (uint32_t)st * BBUF;
        const int ksn = KFULL ? 5 : ((K - c * 72 + 15) >> 4 < 5 ? (K - c * 72 + 15) >> 4 : 5);
#pragma unroll
        for (int ks = 0; ks < 5; ks++) {
            if (!KFULL && ks >= ksn) break;
            uint32_t a[MT][4];
#pragma unroll
            for (int mt = 0; mt < MT; mt++)
                ldsm4t(A0 + a_sw[mt] + (uint32_t)(ks * 16 * APITCH), a[mt]);
#pragma unroll
            for (int q = 0; q < NTL2; q++) {
                uint32_t bo = (uint32_t)((ob + 16 * q + brow) * BPITCH + bseg * 16 + ks * 32);
                uint32_t bh[4];
                ldsm4(Bh + bo, bh);
#pragma unroll
                for (int mt = 0; mt < MT; mt++) {
                    mma16816(acc[mt][2 * q], a[mt], bh[0], bh[1]);
                    mma16816(acc[mt][2 * q + 1], a[mt], bh[2], bh[3]);
                }
            }
            if constexpr (NTL & 1) {
                uint32_t bo = (uint32_t)((ob + 8 * (NTL - 1) + (lane & 7)) * BPITCH +
                                         ((lane >> 3) & 1) * 16 + ks * 32);
                uint32_t bh2[2];
                ldsm2(Bh + bo, bh2);
#pragma unroll
                for (int mt = 0; mt < MT; mt++)
                    mma16816(acc[mt][NTL - 1], a[mt], bh2[0], bh2[1]);
            }
        }
    };

    // ---------------- main pipeline ----------------
    float xb0[4], xb1[4];
    prefetch(0, xb0);
    if (NCHUNK > 1) prefetch(1, xb1);
    __syncthreads();  // prologue zero visible before scatter
    stageB(0, 0);
    scatter(0, 0, xb0);
    cp_wait0();
    __syncthreads();

    for (int c = 0; c < NCHUNK; c++) {
        const int st = c & 1;
        if (c + 2 < NCHUNK) prefetch(c + 2, (c & 1) ? xb1 : xb0);
        if (c + 1 < NCHUNK) stageB(c + 1, st ^ 1);
        mma_chunk(c, st);
        if (c + 1 < NCHUNK) scatter(c + 1, st ^ 1, ((c + 1) & 1) ? xb1 : xb0);
        cp_wait0();
        __syncthreads();
    }

    // ---------------- epilogue: smem transpose -> coalesced STG ----------------
    constexpr int SP = 132;
    float* S = reinterpret_cast<float*>(dsm);  // reuse A region
    __syncthreads();
    {
#pragma unroll
        for (int mt = 0; mt < MT; mt++) {
            const int er0 = rg * (16 * CSPLIT) + mt * 16 + (lane >> 2);
            const int er1 = er0 + 8;
#pragma unroll
            for (int p = 0; p < NTL; p++) {
                int o = ob + p * 8 + (lane & 3) * 2;
                S[o * SP + er0] = acc[mt][p][0];
                S[(o + 1) * SP + er0] = acc[mt][p][1];
                S[o * SP + er1] = acc[mt][p][2];
                S[(o + 1) * SP + er1] = acc[mt][p][3];
            }
        }
    }
    __syncthreads();
    for (int idx = tid; idx < OUT * 128; idx += 256) {
        int o = idx >> 7;
        int rr = idx & 127;
        float val = S[o * SP + rr];
        if (OUT_NCHW) hout[((row0 >> 12) * OUT + o) * 4096 + (row0 & 4095) + rr] = val;
        else hout[o * N + row0 + rr] = val;
    }
}

// ------------------------------- launch ------------------------------------

extern "C" void kernel_launch(void* const* d_in, const int* in_sizes, int n_in,
                              void* d_out, int out_size) {
    const float* x     = (const float*)d_in[0];
    const float* grid0 = (const float*)d_in[1];
    const float* coef0 = (const float*)d_in[2];
    const float* sb0   = (const float*)d_in[3];
    const float* ss0   = (const float*)d_in[4];
    const float* grid1 = (const float*)d_in[5];
    const float* coef1 = (const float*)d_in[6];
    const float* sb1   = (const float*)d_in[7];
    const float* ss1   = (const float*)d_in[8];
    const float* grid2 = (const float*)d_in[9];
    const float* coef2 = (const float*)d_in[10];
    const float* sb2   = (const float*)d_in[11];
    const float* ss2   = (const float*)d_in[12];
    float* out = (float*)d_out;

    int N = in_sizes[0] / 12;
    if (N > MAXN) N = MAXN;

    float *h1, *h2;
    __half *W0, *W1, *W2;
    cudaGetSymbolAddress((void**)&h1, g_h1);
    cudaGetSymbolAddress((void**)&h2, g_h2);
    cudaGetSymbolAddress((void**)&W0, g_W0);
    cudaGetSymbolAddress((void**)&W1, g_W1);
    cudaGetSymbolAddress((void**)&W2, g_W2);

    constexpr int FOLD_TOTAL = 64 * 144 + 64 * 576 + 24 * 576;
    fold_all<<<(FOLD_TOTAL + 255) / 256, 256>>>(coef0, sb0, ss0, coef1, sb1, ss1,
                                                coef2, sb2, ss2, W0, W1, W2);

    auto k0 = kan_mma<12, 64, 108, 144, 2, true, false, 2, 3>;
    auto k1 = kan_mma<64, 64, 576, 576, 8, false, false, 2, 3>;
    auto k2 = kan_mma<64, 24, 576, 576, 8, false, true, 1, 4>;

    constexpr int SM01 = 2 * 80 * 272 + 2 * 64 * 176;  // 66048
    constexpr int SM2  = 2 * 80 * 272 + 2 * 24 * 176;  // 51968
    cudaFuncSetAttribute(k0, cudaFuncAttributeMaxDynamicSharedMemorySize, SM01);
    cudaFuncSetAttribute(k1, cudaFuncAttributeMaxDynamicSharedMemorySize, SM01);
    cudaFuncSetAttribute(k2, cudaFuncAttributeMaxDynamicSharedMemorySize, SM2);

    int blocks = N / 128;
    k0<<<blocks, 256, SM01>>>(x, grid0, W0, h1, N);
    k1<<<blocks, 256, SM01>>>(h1, grid1, W1, h2, N);
    k2<<<blocks, 256, SM2>>>(h2, grid2, W2, out, N);
}

// round 15
// speedup vs baseline: 2.4193x; 1.1154x over previous
#include <cuda_runtime.h>
#include <cuda_fp16.h>
#include <cstdint>

// ---------------------------------------------------------------------------
// KAN 3-layer (12->64->64->24) via warp mma.sync fp16 single-pass.
// Chunk = 72 cols = 8 whole inputs. A K-major pitch 272B, B pitch 176B.
// R15: scatter packs ROW PAIRS into STS.32 (9 stores / 2 tasks) using a
// branchless slot-rotation of the spline window vector.
// ---------------------------------------------------------------------------

#define MAXN (32 * 64 * 64)

__device__ float g_h1[64 * MAXN];
__device__ float g_h2[64 * MAXN];
__device__ __align__(16) __half g_W0[64 * 144];
__device__ __align__(16) __half g_W1[64 * 576];
__device__ __align__(16) __half g_W2[24 * 576];

// ------------------------------- helpers -----------------------------------

__device__ __forceinline__ uint32_t smem_u32(const void* p) {
    uint32_t a;
    asm("{ .reg .u64 t; cvta.to.shared.u64 t, %1; cvt.u32.u64 %0, t; }"
        : "=r"(a) : "l"(p));
    return a;
}
__device__ __forceinline__ void ldsm4(uint32_t addr, uint32_t r[4]) {
    asm volatile("ldmatrix.sync.aligned.m8n8.x4.shared.b16 {%0,%1,%2,%3}, [%4];"
                 : "=r"(r[0]), "=r"(r[1]), "=r"(r[2]), "=r"(r[3]) : "r"(addr));
}
__device__ __forceinline__ void ldsm4t(uint32_t addr, uint32_t r[4]) {
    asm volatile("ldmatrix.sync.aligned.m8n8.x4.trans.shared.b16 {%0,%1,%2,%3}, [%4];"
                 : "=r"(r[0]), "=r"(r[1]), "=r"(r[2]), "=r"(r[3]) : "r"(addr));
}
__device__ __forceinline__ void ldsm2(uint32_t addr, uint32_t r[2]) {
    asm volatile("ldmatrix.sync.aligned.m8n8.x2.shared.b16 {%0,%1}, [%2];"
                 : "=r"(r[0]), "=r"(r[1]) : "r"(addr));
}
__device__ __forceinline__ void mma16816(float c[4], const uint32_t a[4],
                                         uint32_t b0, uint32_t b1) {
    asm volatile(
        "mma.sync.aligned.m16n8k16.row.col.f32.f16.f16.f32 "
        "{%0,%1,%2,%3},{%4,%5,%6,%7},{%8,%9},{%0,%1,%2,%3};"
        : "+f"(c[0]), "+f"(c[1]), "+f"(c[2]), "+f"(c[3])
        : "r"(a[0]), "r"(a[1]), "r"(a[2]), "r"(a[3]), "r"(b0), "r"(b1));
}
__device__ __forceinline__ void sts32(uint32_t addr, uint32_t v) {
    asm volatile("st.shared.b32 [%0], %1;" :: "r"(addr), "r"(v));
}
__device__ __forceinline__ void sts128z(uint32_t addr) {
    asm volatile("st.shared.v4.b32 [%0], {%1,%1,%1,%1};" :: "r"(addr), "r"(0u));
}
__device__ __forceinline__ void cp16(uint32_t dst, const void* src) {
    asm volatile("cp.async.ca.shared.global [%0], [%1], 16;"
                 :: "r"(dst), "l"(src) : "memory");
}
__device__ __forceinline__ void cp_commit() {
    asm volatile("cp.async.commit_group;" ::: "memory");
}
__device__ __forceinline__ void cp_wait0() {
    asm volatile("cp.async.wait_group 0;" ::: "memory");
}
__device__ __forceinline__ uint32_t h2u(__half2 h) {
    return *reinterpret_cast<uint32_t*>(&h);
}

// ------------------------------- fold kernel (fused, all 3 layers) ---------
__global__ void fold_all(const float* c0, const float* b0, const float* s0,
                         const float* c1, const float* b1, const float* s1,
                         const float* c2, const float* b2, const float* s2,
                         __half* W0, __half* W1, __half* W2) {
    int idx = blockIdx.x * blockDim.x + threadIdx.x;
    const float *coef, *sbp, *ss;
    __half* W;
    int IN, OUT, KPAD;
    if (idx < 64 * 144) {
        coef = c0; sbp = b0; ss = s0; W = W0;
        IN = 12; OUT = 64; KPAD = 144;
    } else if (idx < 64 * 144 + 64 * 576) {
        idx -= 64 * 144;
        coef = c1; sbp = b1; ss = s1; W = W1;
        IN = 64; OUT = 64; KPAD = 576;
    } else if (idx < 64 * 144 + 64 * 576 + 24 * 576) {
        idx -= 64 * 144 + 64 * 576;
        coef = c2; sbp = b2; ss = s2; W = W2;
        IN = 64; OUT = 24; KPAD = 576;
    } else return;
    int o = idx / KPAD, k = idx % KPAD;
    float w = 0.0f;
    if (k < IN * 9) {
        int i = k / 9, j = k % 9;
        w = (j == 0) ? sbp[i * OUT + o] : coef[(i * OUT + o) * 8 + (j - 1)] * ss[i * OUT + o];
    }
    W[idx] = __float2half_rn(w);
}

// ------------------------------- layer kernel ------------------------------
template <int IN, int OUT, int K, int KPAD, int NCHUNK, bool IN_NCHW, bool OUT_NCHW,
          int CSPLIT, int MINB>
__global__ void __launch_bounds__(256, MINB)
kan_mma(const float* __restrict__ hin, const float* __restrict__ grid,
        const __half* __restrict__ W, float* __restrict__ hout, int N) {
    constexpr int MT = CSPLIT;
    constexpr int NTL = OUT / 8 / CSPLIT;
    constexpr int NTL2 = NTL / 2;
    constexpr int OUTL = OUT / CSPLIT;
    constexpr int APITCH = 272;
    constexpr int ABUF = 80 * APITCH;
    constexpr int BPITCH = 176;
    constexpr int BBUF = OUT * BPITCH;
    constexpr int SMTOT = 2 * ABUF + 2 * BBUF;
    constexpr bool KFULL = (K % 72 == 0);

    extern __shared__ char dsm[];
    const uint32_t sb = smem_u32(dsm);
    const uint32_t BBASE = sb + 2 * ABUF;

    const int tid = threadIdx.x;
    const int wid = tid >> 5;
    const int lane = tid & 31;
    const int row0 = blockIdx.x * 128;

    const float t0 = __ldg(grid + 0);
    const float invh = 1.0f / (__ldg(grid + 1) - t0);
    const float t11 = __ldg(grid + 11);

    // scatter mapping: thread owns row pair (2rp, 2rp+1), inputs 2*ihalf+{0,1}
    const int rp = tid & 63;
    const int ihalf = (tid >> 6) & 3;
    const int img = row0 >> 12;            // whole CTA in one image
    const int pix0 = (row0 & 4095) + 2 * rp;

    // warp tiling
    const int rg = wid / CSPLIT;
    const int cg = wid % CSPLIT;
    const int ob = cg * OUTL;

    // fragment addressing
    const int gq = lane >> 3;
    const int a_k = (lane & 7) + ((gq >> 1) * 8);
    uint32_t a_sw[MT];
#pragma unroll
    for (int mt = 0; mt < MT; mt++) {
        int a_m = rg * (16 * CSPLIT) + mt * 16 + (gq & 1) * 8;
        a_sw[mt] = (uint32_t)(a_k * APITCH + a_m * 2);
    }
    const int brow = (lane & 7) + 8 * (gq >> 1);
    const int bseg = gq & 1;

    float acc[MT][NTL][4];
#pragma unroll
    for (int mt = 0; mt < MT; mt++)
#pragma unroll
        for (int p = 0; p < NTL; p++)
#pragma unroll
            for (int q = 0; q < 4; q++) acc[mt][p][q] = 0.0f;

    // ---------------- prologue: zero ALL smem ----------------
    for (int z = tid * 16; z < SMTOT; z += 256 * 16) sts128z(sb + z);

    // ---------------- pipeline helpers ----------------
    auto prefetch = [&](int c, float* xr) {
#pragma unroll
        for (int jj = 0; jj < 2; jj++) {
            int i = c * 8 + 2 * ihalf + jj;
#pragma unroll
            for (int rr = 0; rr < 2; rr++) {
                int idx;
                if (IN_NCHW) idx = (img * IN + i) * 4096 + pix0 + rr;
                else idx = i * N + row0 + 2 * rp + rr;
                xr[jj * 2 + rr] = (i < IN) ? __ldg(hin + idx) : 0.0f;
            }
        }
    };

    auto stageB = [&](int c, int st) {
        uint32_t bb = BBASE + (uint32_t)st * BBUF;
        for (int v = tid; v < OUT * 9; v += 256) {
            int o = v / 9, seg = v - o * 9;
            const __half* src = W + o * KPAD + c * 72 + seg * 8;
            cp16(bb + (uint32_t)(o * BPITCH + seg * 16), src);
        }
        cp_commit();
    };

    auto scatter = [&](int c, int st, const float* xr) {
        const uint32_t ah = sb + (uint32_t)st * ABUF + (uint32_t)(rp * 4);
#pragma unroll
        for (int jj = 0; jj < 2; jj++) {
            int il = 2 * ihalf + jj;
            int i = c * 8 + il;
            if (IN < 64 && i >= IN) break;  // layer0 tail only

            uint32_t O[2][4];
            float f0[2];
#pragma unroll
            for (int rr = 0; rr < 2; rr++) {
                float x = xr[jj * 2 + rr];
                f0[rr] = __fdividef(x, 1.0f + __expf(-x));  // silu

                bool inr = (x >= t0) && (x < t11);
                float s = (x - t0) * invh;
                s = fminf(fmaxf(s, 0.0f), 10.999f);
                int m = (int)s;
                float u1 = s - (float)m;
                float um = 1.0f - u1;
                float u2 = u1 * u1, u3 = u2 * u1;
                float fl = inr ? (1.0f / 6.0f) : 0.0f;
                float v0 = um * um * um * fl;
                float v1 = (3.0f * u3 - 6.0f * u2 + 4.0f) * fl;
                float v2 = (-3.0f * u3 + 3.0f * u2 + 3.0f * u1 + 1.0f) * fl;
                float v3 = u3 * fl;

                // mask by basis-index validity (bi = m-3+d in [0,7])
                float w0 = (m >= 3) ? v0 : 0.0f;
                float w1 = (m >= 2 && m <= 9) ? v1 : 0.0f;
                float w2 = (m >= 1 && m <= 8) ? v2 : 0.0f;
                float w3 = (m <= 7) ? v3 : 0.0f;
                uint32_t P0 = h2u(__floats2half2_rn(w0, w1));
                uint32_t P1 = h2u(__floats2half2_rn(w2, w3));

                // slot value at s = w[(s - m + 3) & 7] : rotate [P0,P1,0,0]
                int rho = (3 - m) & 7;
                int q1 = (rho >> 1) & 1, q2 = (rho >> 1) & 2, od = rho & 1;
                // rotate by 1 (P2=P3=0 folded)
                uint32_t A0 = q1 ? P1 : P0;
                uint32_t A1 = q1 ? 0u : P1;
                uint32_t A3 = q1 ? P0 : 0u;
                // rotate by 2
                uint32_t B0 = q2 ? 0u : A0;
                uint32_t B1 = q2 ? A3 : A1;
                uint32_t B2 = q2 ? A0 : 0u;
                uint32_t B3 = q2 ? A1 : A3;
                // odd half-rotation
                uint32_t C0 = od ? __byte_perm(B0, B1, 0x5432) : B0;
                uint32_t C1 = od ? __byte_perm(B1, B2, 0x5432) : B1;
                uint32_t C2 = od ? __byte_perm(B2, B3, 0x5432) : B2;
                uint32_t C3 = od ? __byte_perm(B3, B0, 0x5432) : B3;
                O[rr][0] = C0; O[rr][1] = C1; O[rr][2] = C2; O[rr][3] = C3;
            }

            const uint32_t abase = ah + (uint32_t)((9 * il) * APITCH);
            sts32(abase, h2u(__floats2half2_rn(f0[0], f0[1])));  // silu pair
#pragma unroll
            for (int j2 = 0; j2 < 4; j2++) {
                uint32_t qlo = __byte_perm(O[0][j2], O[1][j2], 0x5410);
                uint32_t qhi = __byte_perm(O[0][j2], O[1][j2], 0x7632);
                sts32(abase + (uint32_t)((1 + 2 * j2) * APITCH), qlo);
                sts32(abase + (uint32_t)((2 + 2 * j2) * APITCH), qhi);
            }
        }
    };

    auto mma_chunk = [&](int c, int st) {
        const uint32_t A0a = sb + (uint32_t)st * ABUF;
        const uint32_t Bh = BBASE + (uint32_t)st * BBUF;
        const int ksn = KFULL ? 5 : ((K - c * 72 + 15) >> 4 < 5 ? (K - c * 72 + 15) >> 4 : 5);
#pragma unroll
        for (int ks = 0; ks < 5; ks++) {
            if (!KFULL && ks >= ksn) break;
            uint32_t a[MT][4];
#pragma unroll
            for (int mt = 0; mt < MT; mt++)
                ldsm4t(A0a + a_sw[mt] + (uint32_t)(ks * 16 * APITCH), a[mt]);
#pragma unroll
            for (int q = 0; q < NTL2; q++) {
                uint32_t bo = (uint32_t)((ob + 16 * q + brow) * BPITCH + bseg * 16 + ks * 32);
                uint32_t bh[4];
                ldsm4(Bh + bo, bh);
#pragma unroll
                for (int mt = 0; mt < MT; mt++) {
                    mma16816(acc[mt][2 * q], a[mt], bh[0], bh[1]);
                    mma16816(acc[mt][2 * q + 1], a[mt], bh[2], bh[3]);
                }
            }
            if constexpr (NTL & 1) {
                uint32_t bo = (uint32_t)((ob + 8 * (NTL - 1) + (lane & 7)) * BPITCH +
                                         ((lane >> 3) & 1) * 16 + ks * 32);
                uint32_t bh2[2];
                ldsm2(Bh + bo, bh2);
#pragma unroll
                for (int mt = 0; mt < MT; mt++)
                    mma16816(acc[mt][NTL - 1], a[mt], bh2[0], bh2[1]);
            }
        }
    };

    // ---------------- main pipeline ----------------
    float xb0[4], xb1[4];
    prefetch(0, xb0);
    if (NCHUNK > 1) prefetch(1, xb1);
    __syncthreads();  // prologue zero visible before scatter
    stageB(0, 0);
    scatter(0, 0, xb0);
    cp_wait0();
    __syncthreads();

    for (int c = 0; c < NCHUNK; c++) {
        const int st = c & 1;
        if (c + 2 < NCHUNK) prefetch(c + 2, (c & 1) ? xb1 : xb0);
        if (c + 1 < NCHUNK) stageB(c + 1, st ^ 1);
        mma_chunk(c, st);
        if (c + 1 < NCHUNK) scatter(c + 1, st ^ 1, ((c + 1) & 1) ? xb1 : xb0);
        cp_wait0();
        __syncthreads();
    }

    // ---------------- epilogue: smem transpose -> coalesced STG ----------------
    constexpr int SP = 132;
    float* S = reinterpret_cast<float*>(dsm);  // reuse A region
    __syncthreads();
    {
#pragma unroll
        for (int mt = 0; mt < MT; mt++) {
            const int er0 = rg * (16 * CSPLIT) + mt * 16 + (lane >> 2);
            const int er1 = er0 + 8;
#pragma unroll
            for (int p = 0; p < NTL; p++) {
                int o = ob + p * 8 + (lane & 3) * 2;
                S[o * SP + er0] = acc[mt][p][0];
                S[(o + 1) * SP + er0] = acc[mt][p][1];
                S[o * SP + er1] = acc[mt][p][2];
                S[(o + 1) * SP + er1] = acc[mt][p][3];
            }
        }
    }
    __syncthreads();
    for (int idx = tid; idx < OUT * 128; idx += 256) {
        int o = idx >> 7;
        int rr = idx & 127;
        float val = S[o * SP + rr];
        if (OUT_NCHW) hout[((row0 >> 12) * OUT + o) * 4096 + (row0 & 4095) + rr] = val;
        else hout[o * N + row0 + rr] = val;
    }
}

// ------------------------------- launch ------------------------------------

extern "C" void kernel_launch(void* const* d_in, const int* in_sizes, int n_in,
                              void* d_out, int out_size) {
    const float* x     = (const float*)d_in[0];
    const float* grid0 = (const float*)d_in[1];
    const float* coef0 = (const float*)d_in[2];
    const float* sb0   = (const float*)d_in[3];
    const float* ss0   = (const float*)d_in[4];
    const float* grid1 = (const float*)d_in[5];
    const float* coef1 = (const float*)d_in[6];
    const float* sb1   = (const float*)d_in[7];
    const float* ss1   = (const float*)d_in[8];
    const float* grid2 = (const float*)d_in[9];
    const float* coef2 = (const float*)d_in[10];
    const float* sb2   = (const float*)d_in[11];
    const float* ss2   = (const float*)d_in[12];
    float* out = (float*)d_out;

    int N = in_sizes[0] / 12;
    if (N > MAXN) N = MAXN;

    float *h1, *h2;
    __half *W0, *W1, *W2;
    cudaGetSymbolAddress((void**)&h1, g_h1);
    cudaGetSymbolAddress((void**)&h2, g_h2);
    cudaGetSymbolAddress((void**)&W0, g_W0);
    cudaGetSymbolAddress((void**)&W1, g_W1);
    cudaGetSymbolAddress((void**)&W2, g_W2);

    constexpr int FOLD_TOTAL = 64 * 144 + 64 * 576 + 24 * 576;
    fold_all<<<(FOLD_TOTAL + 255) / 256, 256>>>(coef0, sb0, ss0, coef1, sb1, ss1,
                                                coef2, sb2, ss2, W0, W1, W2);

    auto k0 = kan_mma<12, 64, 108, 144, 2, true, false, 2, 3>;
    auto k1 = kan_mma<64, 64, 576, 576, 8, false, false, 2, 3>;
    auto k2 = kan_mma<64, 24, 576, 576, 8, false, true, 1, 4>;

    constexpr int SM01 = 2 * 80 * 272 + 2 * 64 * 176;  // 66048
    constexpr int SM2  = 2 * 80 * 272 + 2 * 24 * 176;  // 51968
    cudaFuncSetAttribute(k0, cudaFuncAttributeMaxDynamicSharedMemorySize, SM01);
    cudaFuncSetAttribute(k1, cudaFuncAttributeMaxDynamicSharedMemorySize, SM01);
    cudaFuncSetAttribute(k2, cudaFuncAttributeMaxDynamicSharedMemorySize, SM2);

    int blocks = N / 128;
    k0<<<blocks, 256, SM01>>>(x, grid0, W0, h1, N);
    k1<<<blocks, 256, SM01>>>(h1, grid1, W1, h2, N);
    k2<<<blocks, 256, SM2>>>(h2, grid2, W2, out, N);
}

// round 16
// speedup vs baseline: 2.4303x; 1.0046x over previous
#include <cuda_runtime.h>
#include <cuda_fp16.h>
#include <cstdint>

// ---------------------------------------------------------------------------
// KAN 3-layer (12->64->64->24) via warp mma.sync fp16 single-pass.
// Chunk = 72 cols = 8 whole inputs. A K-major pitch 272B, B pitch 176B.
// R16: scatter packs ROW QUADS into st.shared.v2.b32 (9 stores per
// input x 4 rows); one input per thread per chunk; float4 x prefetch.
// ---------------------------------------------------------------------------

#define MAXN (32 * 64 * 64)

__device__ float g_h1[64 * MAXN];
__device__ float g_h2[64 * MAXN];
__device__ __align__(16) __half g_W0[64 * 144];
__device__ __align__(16) __half g_W1[64 * 576];
__device__ __align__(16) __half g_W2[24 * 576];

// ------------------------------- helpers -----------------------------------

__device__ __forceinline__ uint32_t smem_u32(const void* p) {
    uint32_t a;
    asm("{ .reg .u64 t; cvta.to.shared.u64 t, %1; cvt.u32.u64 %0, t; }"
        : "=r"(a) : "l"(p));
    return a;
}
__device__ __forceinline__ void ldsm4(uint32_t addr, uint32_t r[4]) {
    asm volatile("ldmatrix.sync.aligned.m8n8.x4.shared.b16 {%0,%1,%2,%3}, [%4];"
                 : "=r"(r[0]), "=r"(r[1]), "=r"(r[2]), "=r"(r[3]) : "r"(addr));
}
__device__ __forceinline__ void ldsm4t(uint32_t addr, uint32_t r[4]) {
    asm volatile("ldmatrix.sync.aligned.m8n8.x4.trans.shared.b16 {%0,%1,%2,%3}, [%4];"
                 : "=r"(r[0]), "=r"(r[1]), "=r"(r[2]), "=r"(r[3]) : "r"(addr));
}
__device__ __forceinline__ void ldsm2(uint32_t addr, uint32_t r[2]) {
    asm volatile("ldmatrix.sync.aligned.m8n8.x2.shared.b16 {%0,%1}, [%2];"
                 : "=r"(r[0]), "=r"(r[1]) : "r"(addr));
}
__device__ __forceinline__ void mma16816(float c[4], const uint32_t a[4],
                                         uint32_t b0, uint32_t b1) {
    asm volatile(
        "mma.sync.aligned.m16n8k16.row.col.f32.f16.f16.f32 "
        "{%0,%1,%2,%3},{%4,%5,%6,%7},{%8,%9},{%0,%1,%2,%3};"
        : "+f"(c[0]), "+f"(c[1]), "+f"(c[2]), "+f"(c[3])
        : "r"(a[0]), "r"(a[1]), "r"(a[2]), "r"(a[3]), "r"(b0), "r"(b1));
}
__device__ __forceinline__ void sts64(uint32_t addr, uint32_t v0, uint32_t v1) {
    asm volatile("st.shared.v2.b32 [%0], {%1,%2};" :: "r"(addr), "r"(v0), "r"(v1));
}
__device__ __forceinline__ void sts128z(uint32_t addr) {
    asm volatile("st.shared.v4.b32 [%0], {%1,%1,%1,%1};" :: "r"(addr), "r"(0u));
}
__device__ __forceinline__ void cp16(uint32_t dst, const void* src) {
    asm volatile("cp.async.ca.shared.global [%0], [%1], 16;"
                 :: "r"(dst), "l"(src) : "memory");
}
__device__ __forceinline__ void cp_commit() {
    asm volatile("cp.async.commit_group;" ::: "memory");
}
__device__ __forceinline__ void cp_wait0() {
    asm volatile("cp.async.wait_group 0;" ::: "memory");
}
__device__ __forceinline__ uint32_t h2u(__half2 h) {
    return *reinterpret_cast<uint32_t*>(&h);
}

// ------------------------------- fold kernel (fused, all 3 layers) ---------
__global__ void fold_all(const float* c0, const float* b0, const float* s0,
                         const float* c1, const float* b1, const float* s1,
                         const float* c2, const float* b2, const float* s2,
                         __half* W0, __half* W1, __half* W2) {
    int idx = blockIdx.x * blockDim.x + threadIdx.x;
    const float *coef, *sbp, *ss;
    __half* W;
    int IN, OUT, KPAD;
    if (idx < 64 * 144) {
        coef = c0; sbp = b0; ss = s0; W = W0;
        IN = 12; OUT = 64; KPAD = 144;
    } else if (idx < 64 * 144 + 64 * 576) {
        idx -= 64 * 144;
        coef = c1; sbp = b1; ss = s1; W = W1;
        IN = 64; OUT = 64; KPAD = 576;
    } else if (idx < 64 * 144 + 64 * 576 + 24 * 576) {
        idx -= 64 * 144 + 64 * 576;
        coef = c2; sbp = b2; ss = s2; W = W2;
        IN = 64; OUT = 24; KPAD = 576;
    } else return;
    int o = idx / KPAD, k = idx % KPAD;
    float w = 0.0f;
    if (k < IN * 9) {
        int i = k / 9, j = k % 9;
        w = (j == 0) ? sbp[i * OUT + o] : coef[(i * OUT + o) * 8 + (j - 1)] * ss[i * OUT + o];
    }
    W[idx] = __float2half_rn(w);
}

// ------------------------------- layer kernel ------------------------------
template <int IN, int OUT, int K, int KPAD, int NCHUNK, bool IN_NCHW, bool OUT_NCHW,
          int CSPLIT, int MINB>
__global__ void __launch_bounds__(256, MINB)
kan_mma(const float* __restrict__ hin, const float* __restrict__ grid,
        const __half* __restrict__ W, float* __restrict__ hout, int N) {
    constexpr int MT = CSPLIT;
    constexpr int NTL = OUT / 8 / CSPLIT;
    constexpr int NTL2 = NTL / 2;
    constexpr int OUTL = OUT / CSPLIT;
    constexpr int APITCH = 272;
    constexpr int ABUF = 80 * APITCH;
    constexpr int BPITCH = 176;
    constexpr int BBUF = OUT * BPITCH;
    constexpr int SMTOT = 2 * ABUF + 2 * BBUF;
    constexpr bool KFULL = (K % 72 == 0);

    extern __shared__ char dsm[];
    const uint32_t sb = smem_u32(dsm);
    const uint32_t BBASE = sb + 2 * ABUF;

    const int tid = threadIdx.x;
    const int wid = tid >> 5;
    const int lane = tid & 31;
    const int row0 = blockIdx.x * 128;

    const float t0 = __ldg(grid + 0);
    const float invh = 1.0f / (__ldg(grid + 1) - t0);
    const float t11 = __ldg(grid + 11);

    // scatter mapping: thread owns row quad (4q..4q+3), one input per chunk
    const int q = tid & 31;
    const int il = tid >> 5;  // 0..7
    const int img = row0 >> 12;
    const int pix0 = (row0 & 4095) + 4 * q;

    // warp tiling
    const int rg = wid / CSPLIT;
    const int cg = wid % CSPLIT;
    const int ob = cg * OUTL;

    // fragment addressing
    const int gq = lane >> 3;
    const int a_k = (lane & 7) + ((gq >> 1) * 8);
    uint32_t a_sw[MT];
#pragma unroll
    for (int mt = 0; mt < MT; mt++) {
        int a_m = rg * (16 * CSPLIT) + mt * 16 + (gq & 1) * 8;
        a_sw[mt] = (uint32_t)(a_k * APITCH + a_m * 2);
    }
    const int brow = (lane & 7) + 8 * (gq >> 1);
    const int bseg = gq & 1;

    float acc[MT][NTL][4];
#pragma unroll
    for (int mt = 0; mt < MT; mt++)
#pragma unroll
        for (int p = 0; p < NTL; p++)
#pragma unroll
            for (int qq = 0; qq < 4; qq++) acc[mt][p][qq] = 0.0f;

    // ---------------- prologue: zero ALL smem ----------------
    for (int z = tid * 16; z < SMTOT; z += 256 * 16) sts128z(sb + z);

    // ---------------- pipeline helpers ----------------
    auto prefetch = [&](int c, float4& xr) {
        int i = c * 8 + il;
        if (i < IN) {
            const float* src;
            if (IN_NCHW) src = hin + (img * IN + i) * 4096 + pix0;
            else src = hin + i * N + row0 + 4 * q;
            xr = *reinterpret_cast<const float4*>(src);
        } else {
            xr = make_float4(0.f, 0.f, 0.f, 0.f);
        }
    };

    auto stageB = [&](int c, int st) {
        uint32_t bb = BBASE + (uint32_t)st * BBUF;
        for (int v = tid; v < OUT * 9; v += 256) {
            int o = v / 9, seg = v - o * 9;
            const __half* src = W + o * KPAD + c * 72 + seg * 8;
            cp16(bb + (uint32_t)(o * BPITCH + seg * 16), src);
        }
        cp_commit();
    };

    auto scatter = [&](int c, int st, const float4& xr) {
        int i = c * 8 + il;
        if (IN < 64 && i >= IN) return;  // layer0 tail only
        const uint32_t abase = sb + (uint32_t)st * ABUF + (uint32_t)(q * 8) +
                               (uint32_t)((9 * il) * APITCH);
        float xv[4] = {xr.x, xr.y, xr.z, xr.w};
        uint32_t O[4][4];
        float f0[4];
#pragma unroll
        for (int rr = 0; rr < 4; rr++) {
            float x = xv[rr];
            f0[rr] = __fdividef(x, 1.0f + __expf(-x));  // silu

            bool inr = (x >= t0) && (x < t11);
            float s = (x - t0) * invh;
            s = fminf(fmaxf(s, 0.0f), 10.999f);
            int m = (int)s;
            float u1 = s - (float)m;
            float um = 1.0f - u1;
            float u2 = u1 * u1, u3 = u2 * u1;
            float fl = inr ? (1.0f / 6.0f) : 0.0f;
            float v0 = um * um * um * fl;
            float v1 = (3.0f * u3 - 6.0f * u2 + 4.0f) * fl;
            float v2 = (-3.0f * u3 + 3.0f * u2 + 3.0f * u1 + 1.0f) * fl;
            float v3 = u3 * fl;

            // mask by basis-index validity (bi = m-3+d in [0,7])
            float w0 = (m >= 3) ? v0 : 0.0f;
            float w1 = (m >= 2 && m <= 9) ? v1 : 0.0f;
            float w2 = (m >= 1 && m <= 8) ? v2 : 0.0f;
            float w3 = (m <= 7) ? v3 : 0.0f;
            uint32_t P0 = h2u(__floats2half2_rn(w0, w1));
            uint32_t P1 = h2u(__floats2half2_rn(w2, w3));

            // slot value at s = w[(s - m + 3) & 7] : rotate [P0,P1,0,0]
            int rho = (3 - m) & 7;
            int q1 = (rho >> 1) & 1, q2 = (rho >> 1) & 2, od = rho & 1;
            uint32_t A0 = q1 ? P1 : P0;
            uint32_t A1 = q1 ? 0u : P1;
            uint32_t A3 = q1 ? P0 : 0u;
            uint32_t B0 = q2 ? 0u : A0;
            uint32_t B1 = q2 ? A3 : A1;
            uint32_t B2 = q2 ? A0 : 0u;
            uint32_t B3 = q2 ? A1 : A3;
            uint32_t C0 = od ? __byte_perm(B0, B1, 0x5432) : B0;
            uint32_t C1 = od ? __byte_perm(B1, B2, 0x5432) : B1;
            uint32_t C2 = od ? __byte_perm(B2, B3, 0x5432) : B2;
            uint32_t C3 = od ? __byte_perm(B3, B0, 0x5432) : B3;
            O[rr][0] = C0; O[rr][1] = C1; O[rr][2] = C2; O[rr][3] = C3;
        }

        // silu quad (slot 0)
        sts64(abase, h2u(__floats2half2_rn(f0[0], f0[1])),
              h2u(__floats2half2_rn(f0[2], f0[3])));
        // slots 1..8, two per j2, quad-interleaved
#pragma unroll
        for (int j2 = 0; j2 < 4; j2++) {
            uint32_t lo01 = __byte_perm(O[0][j2], O[1][j2], 0x5410);
            uint32_t lo23 = __byte_perm(O[2][j2], O[3][j2], 0x5410);
            uint32_t hi01 = __byte_perm(O[0][j2], O[1][j2], 0x7632);
            uint32_t hi23 = __byte_perm(O[2][j2], O[3][j2], 0x7632);
            sts64(abase + (uint32_t)((1 + 2 * j2) * APITCH), lo01, lo23);
            sts64(abase + (uint32_t)((2 + 2 * j2) * APITCH), hi01, hi23);
        }
    };

    auto mma_chunk = [&](int c, int st) {
        const uint32_t A0a = sb + (uint32_t)st * ABUF;
        const uint32_t Bh = BBASE + (uint32_t)st * BBUF;
        const int ksn = KFULL ? 5 : ((K - c * 72 + 15) >> 4 < 5 ? (K - c * 72 + 15) >> 4 : 5);
#pragma unroll
        for (int ks = 0; ks < 5; ks++) {
            if (!KFULL && ks >= ksn) break;
            uint32_t a[MT][4];
#pragma unroll
            for (int mt = 0; mt < MT; mt++)
                ldsm4t(A0a + a_sw[mt] + (uint32_t)(ks * 16 * APITCH), a[mt]);
#pragma unroll
            for (int qq = 0; qq < NTL2; qq++) {
                uint32_t bo = (uint32_t)((ob + 16 * qq + brow) * BPITCH + bseg * 16 + ks * 32);
                uint32_t bh[4];
                ldsm4(Bh + bo, bh);
#pragma unroll
                for (int mt = 0; mt < MT; mt++) {
                    mma16816(acc[mt][2 * qq], a[mt], bh[0], bh[1]);
                    mma16816(acc[mt][2 * qq + 1], a[mt], bh[2], bh[3]);
                }
            }
            if constexpr (NTL & 1) {
                uint32_t bo = (uint32_t)((ob + 8 * (NTL - 1) + (lane & 7)) * BPITCH +
                                         ((lane >> 3) & 1) * 16 + ks * 32);
                uint32_t bh2[2];
                ldsm2(Bh + bo, bh2);
#pragma unroll
                for (int mt = 0; mt < MT; mt++)
                    mma16816(acc[mt][NTL - 1], a[mt], bh2[0], bh2[1]);
            }
        }
    };

    // ---------------- main pipeline ----------------
    float4 xb0, xb1;
    prefetch(0, xb0);
    if (NCHUNK > 1) prefetch(1, xb1);
    __syncthreads();  // prologue zero visible before scatter
    stageB(0, 0);
    scatter(0, 0, xb0);
    cp_wait0();
    __syncthreads();

    for (int c = 0; c < NCHUNK; c++) {
        const int st = c & 1;
        if (c + 2 < NCHUNK) prefetch(c + 2, (c & 1) ? xb1 : xb0);
        if (c + 1 < NCHUNK) stageB(c + 1, st ^ 1);
        mma_chunk(c, st);
        if (c + 1 < NCHUNK) scatter(c + 1, st ^ 1, ((c + 1) & 1) ? xb1 : xb0);
        cp_wait0();
        __syncthreads();
    }

    // ---------------- epilogue: smem transpose -> coalesced STG ----------------
    constexpr int SP = 132;
    float* S = reinterpret_cast<float*>(dsm);  // reuse A region
    __syncthreads();
    {
#pragma unroll
        for (int mt = 0; mt < MT; mt++) {
            const int er0 = rg * (16 * CSPLIT) + mt * 16 + (lane >> 2);
            const int er1 = er0 + 8;
#pragma unroll
            for (int p = 0; p < NTL; p++) {
                int o = ob + p * 8 + (lane & 3) * 2;
                S[o * SP + er0] = acc[mt][p][0];
                S[(o + 1) * SP + er0] = acc[mt][p][1];
                S[o * SP + er1] = acc[mt][p][2];
                S[(o + 1) * SP + er1] = acc[mt][p][3];
            }
        }
    }
    __syncthreads();
    for (int idx = tid; idx < OUT * 128; idx += 256) {
        int o = idx >> 7;
        int rr = idx & 127;
        float val = S[o * SP + rr];
        if (OUT_NCHW) hout[((row0 >> 12) * OUT + o) * 4096 + (row0 & 4095) + rr] = val;
        else hout[o * N + row0 + rr] = val;
    }
}

// ------------------------------- launch ------------------------------------

extern "C" void kernel_launch(void* const* d_in, const int* in_sizes, int n_in,
                              void* d_out, int out_size) {
    const float* x     = (const float*)d_in[0];
    const float* grid0 = (const float*)d_in[1];
    const float* coef0 = (const float*)d_in[2];
    const float* sb0   = (const float*)d_in[3];
    const float* ss0   = (const float*)d_in[4];
    const float* grid1 = (const float*)d_in[5];
    const float* coef1 = (const float*)d_in[6];
    const float* sb1   = (const float*)d_in[7];
    const float* ss1   = (const float*)d_in[8];
    const float* grid2 = (const float*)d_in[9];
    const float* coef2 = (const float*)d_in[10];
    const float* sb2   = (const float*)d_in[11];
    const float* ss2   = (const float*)d_in[12];
    float* out = (float*)d_out;

    int N = in_sizes[0] / 12;
    if (N > MAXN) N = MAXN;

    float *h1, *h2;
    __half *W0, *W1, *W2;
    cudaGetSymbolAddress((void**)&h1, g_h1);
    cudaGetSymbolAddress((void**)&h2, g_h2);
    cudaGetSymbolAddress((void**)&W0, g_W0);
    cudaGetSymbolAddress((void**)&W1, g_W1);
    cudaGetSymbolAddress((void**)&W2, g_W2);

    constexpr int FOLD_TOTAL = 64 * 144 + 64 * 576 + 24 * 576;
    fold_all<<<(FOLD_TOTAL + 255) / 256, 256>>>(coef0, sb0, ss0, coef1, sb1, ss1,
                                                coef2, sb2, ss2, W0, W1, W2);

    auto k0 = kan_mma<12, 64, 108, 144, 2, true, false, 2, 3>;
    auto k1 = kan_mma<64, 64, 576, 576, 8, false, false, 2, 3>;
    auto k2 = kan_mma<64, 24, 576, 576, 8, false, true, 1, 4>;

    constexpr int SM01 = 2 * 80 * 272 + 2 * 64 * 176;  // 66048
    constexpr int SM2  = 2 * 80 * 272 + 2 * 24 * 176;  // 51968
    cudaFuncSetAttribute(k0, cudaFuncAttributeMaxDynamicSharedMemorySize, SM01);
    cudaFuncSetAttribute(k1, cudaFuncAttributeMaxDynamicSharedMemorySize, SM01);
    cudaFuncSetAttribute(k2, cudaFuncAttributeMaxDynamicSharedMemorySize, SM2);

    int blocks = N / 128;
    k0<<<blocks, 256, SM01>>>(x, grid0, W0, h1, N);
    k1<<<blocks, 256, SM01>>>(h1, grid1, W1, h2, N);
    k2<<<blocks, 256, SM2>>>(h2, grid2, W2, out, N);
}